// round 3
// baseline (speedup 1.0000x reference)
#include <cuda_runtime.h>
#include <cstdint>

#define D_MODEL 1024
#define SEQ     2048
#define BATCH   4
#define NHEAD   16
#define DHEAD   64
#define MTOT    (BATCH*SEQ)   // 8192
#define LN_EPS  1e-5f

// ---------------------------------------------------------------------------
// Scratch (no cudaMalloc allowed)
// ---------------------------------------------------------------------------
__device__ float g_q[(size_t)MTOT * D_MODEL];
__device__ float g_k[(size_t)MTOT * D_MODEL];
__device__ float g_v[(size_t)MTOT * D_MODEL];
__device__ float g_attn[(size_t)MTOT * D_MODEL];
__device__ float g_x[(size_t)MTOT * D_MODEL];
__device__ float g_bxr[(size_t)MTOT * D_MODEL];          // tf32-rounded batch
__device__ float g_wr[4][(size_t)D_MODEL * D_MODEL];     // tf32-rounded weights

// ---------------------------------------------------------------------------
// Helpers
// ---------------------------------------------------------------------------
__device__ __forceinline__ uint32_t s2u(const void* p) {
    uint32_t a;
    asm("{ .reg .u64 t; cvta.to.shared.u64 t, %1; cvt.u32.u64 %0, t; }"
        : "=r"(a) : "l"(p));
    return a;
}
__device__ __forceinline__ uint32_t f2tf32(float x) {
    uint32_t u;
    asm("cvt.rna.tf32.f32 %0, %1;" : "=r"(u) : "f"(x));
    return u;
}

// ---------------------------------------------------------------------------
// Round fp32 -> tf32 (rna), elementwise
// ---------------------------------------------------------------------------
__global__ __launch_bounds__(256)
void round_tf32_kernel(const float* __restrict__ in, float* __restrict__ out, int n4)
{
    int i = blockIdx.x * blockDim.x + threadIdx.x;
    if (i < n4) {
        float4 f = ((const float4*)in)[i];
        float4 o;
        o.x = __uint_as_float(f2tf32(f.x));
        o.y = __uint_as_float(f2tf32(f.y));
        o.z = __uint_as_float(f2tf32(f.z));
        o.w = __uint_as_float(f2tf32(f.w));
        ((float4*)out)[i] = o;
    }
}

// ---------------------------------------------------------------------------
// tf32 mma.sync GEMM: C[M,N] = A[M,K] @ W[N,K]^T + bias (+resid)
// CTA tile 128x128, BK=16, 2-stage cp.async pipeline, 256 threads (8 warps).
// Warp grid 2(m) x 4(n); warp tile 64x32 -> 4 m16-tiles x 4 n8-tiles.
// Smem rows padded to 20 floats (80B): ldmatrix 8-row phases conflict-free.
// Operands must be tf32-pre-rounded (mma truncates to tf32 internally).
// ---------------------------------------------------------------------------
#define GPITCH 20   // floats per smem row (16 data + 4 pad)

template<bool RESID>
__global__ __launch_bounds__(256, 2)
void gemm_mma(const float* __restrict__ A, const float* __restrict__ W,
              const float* __restrict__ bias, const float* __restrict__ resid,
              float* __restrict__ C, int M, int N, int K)
{
    __shared__ __align__(128) float As[2][128 * GPITCH];
    __shared__ __align__(128) float Bs[2][128 * GPITCH];

    const int tid  = threadIdx.x;
    const int wid  = tid >> 5;
    const int lane = tid & 31;
    const int wm   = wid & 1;        // 0..1
    const int wn   = wid >> 1;       // 0..3
    const int m0   = blockIdx.y * 128;
    const int n0   = blockIdx.x * 128;

    const uint32_t sA = s2u(As);
    const uint32_t sB = s2u(Bs);
    const int NCH = K / 16;          // 64

    // cp.async: each thread copies 2 granules of A and 2 of B per chunk
    const int r_ld = tid >> 2;           // 0..63 base row
    const int g_ld = tid & 3;            // granule 0..3
    const float* Abase = A + (size_t)m0 * K + g_ld * 4;
    const float* Wbase = W + (size_t)n0 * K + g_ld * 4;

    auto issue = [&](int c) {
        if (c < NCH) {
            int st = c & 1;
            uint32_t da = sA + st * (128 * GPITCH * 4);
            uint32_t db = sB + st * (128 * GPITCH * 4);
            long ko = (long)c * 16;
#pragma unroll
            for (int q = 0; q < 2; q++) {
                int r = r_ld + q * 64;
                uint32_t d  = da + r * (GPITCH * 4) + g_ld * 16;
                const float* s = Abase + (size_t)r * K + ko;
                asm volatile("cp.async.cg.shared.global [%0], [%1], 16;"
                             :: "r"(d), "l"(s) : "memory");
                uint32_t d2 = db + r * (GPITCH * 4) + g_ld * 16;
                const float* s2 = Wbase + (size_t)r * K + ko;
                asm volatile("cp.async.cg.shared.global [%0], [%1], 16;"
                             :: "r"(d2), "l"(s2) : "memory");
            }
        }
        asm volatile("cp.async.commit_group;" ::: "memory");
    };

    float acc[4][4][4];
#pragma unroll
    for (int i = 0; i < 4; i++)
#pragma unroll
        for (int j = 0; j < 4; j++)
#pragma unroll
            for (int k = 0; k < 4; k++) acc[i][j][k] = 0.0f;

    // Per-lane ldmatrix row/granule decomposition
    const int laneA_r = ((lane >> 3) & 1) * 8 + (lane & 7);
    const int laneA_g = lane >> 4;              // 0..1
    const int laneB_r = (lane >> 4) * 8 + (lane & 7);
    const int laneB_g = (lane >> 3) & 1;        // 0..1

    issue(0);

    for (int c = 0; c < NCH; c++) {
        issue(c + 1);
        asm volatile("cp.async.wait_group 1;" ::: "memory");
        __syncthreads();

        int st = c & 1;
        uint32_t aSt = sA + st * (128 * GPITCH * 4);
        uint32_t bSt = sB + st * (128 * GPITCH * 4);

#pragma unroll
        for (int j = 0; j < 2; j++) {          // two k8 steps
            uint32_t aF[4][4], bF[2][4];
#pragma unroll
            for (int mt = 0; mt < 4; mt++) {
                uint32_t addr = aSt + (wm * 64 + mt * 16 + laneA_r) * (GPITCH * 4)
                                    + (laneA_g + 2 * j) * 16;
                asm volatile("ldmatrix.sync.aligned.m8n8.x4.shared.b16 {%0,%1,%2,%3}, [%4];"
                             : "=r"(aF[mt][0]), "=r"(aF[mt][1]),
                               "=r"(aF[mt][2]), "=r"(aF[mt][3])
                             : "r"(addr));
            }
#pragma unroll
            for (int np = 0; np < 2; np++) {
                uint32_t addr = bSt + (wn * 32 + np * 16 + laneB_r) * (GPITCH * 4)
                                    + (laneB_g + 2 * j) * 16;
                asm volatile("ldmatrix.sync.aligned.m8n8.x4.shared.b16 {%0,%1,%2,%3}, [%4];"
                             : "=r"(bF[np][0]), "=r"(bF[np][1]),
                               "=r"(bF[np][2]), "=r"(bF[np][3])
                             : "r"(addr));
            }
#pragma unroll
            for (int mt = 0; mt < 4; mt++) {
#pragma unroll
                for (int t = 0; t < 4; t++) {
                    uint32_t b0 = bF[t >> 1][(t & 1) * 2];
                    uint32_t b1 = bF[t >> 1][(t & 1) * 2 + 1];
                    asm volatile(
                        "mma.sync.aligned.m16n8k8.row.col.f32.tf32.tf32.f32 "
                        "{%0,%1,%2,%3}, {%4,%5,%6,%7}, {%8,%9}, {%0,%1,%2,%3};"
                        : "+f"(acc[mt][t][0]), "+f"(acc[mt][t][1]),
                          "+f"(acc[mt][t][2]), "+f"(acc[mt][t][3])
                        : "r"(aF[mt][0]), "r"(aF[mt][1]),
                          "r"(aF[mt][2]), "r"(aF[mt][3]),
                          "r"(b0), "r"(b1));
                }
            }
        }
        __syncthreads();
    }

    // Epilogue
    const int rb = lane >> 2;
    const int cb = (lane & 3) * 2;
#pragma unroll
    for (int mt = 0; mt < 4; mt++) {
#pragma unroll
        for (int t = 0; t < 4; t++) {
            int n = n0 + wn * 32 + t * 8 + cb;
            float2 bv = *(const float2*)(bias + n);
            int row0 = m0 + wm * 64 + mt * 16 + rb;
            int row1 = row0 + 8;
            float2 o0, o1;
            o0.x = acc[mt][t][0] + bv.x;
            o0.y = acc[mt][t][1] + bv.y;
            o1.x = acc[mt][t][2] + bv.x;
            o1.y = acc[mt][t][3] + bv.y;
            if (RESID) {
                float2 r0 = *(const float2*)(resid + (size_t)row0 * N + n);
                float2 r1 = *(const float2*)(resid + (size_t)row1 * N + n);
                o0.x += r0.x; o0.y += r0.y;
                o1.x += r1.x; o1.y += r1.y;
            }
            *(float2*)(C + (size_t)row0 * N + n) = o0;
            *(float2*)(C + (size_t)row1 * N + n) = o1;
        }
    }
}

// ---------------------------------------------------------------------------
// Flash attention (fp32, online softmax), vectorized inner loops.
// grid = (SEQ/64, NHEAD, BATCH), 256 threads (8 warps).
// Output rounded to tf32 (feeds tf32 out-proj GEMM).
// ---------------------------------------------------------------------------
__global__ __launch_bounds__(256)
void attn_kernel(const float* __restrict__ Q,
                 const float* __restrict__ Kg,
                 const float* __restrict__ Vg,
                 float* __restrict__ Og)
{
    __shared__ float sQ[64][64];    // [row][d]
    __shared__ float sKV[64][64];   // K phase: [d][c] ; V phase: [c][d]
    __shared__ float sP[64][64];    // [row][c]

    const int qt   = blockIdx.x;
    const int h    = blockIdx.y;
    const int b    = blockIdx.z;
    const int tid  = threadIdx.x;
    const int warp = tid >> 5;
    const int lane = tid & 31;

    const size_t base = ((size_t)b * SEQ) * D_MODEL + (size_t)h * DHEAD;

    for (int i = tid; i < 1024; i += 256) {
        int r  = i >> 4;
        int c4 = (i & 15) * 4;
        float4 f = *(const float4*)(Q + base + (size_t)(qt * 64 + r) * D_MODEL + c4);
        *(float4*)&sQ[r][c4] = f;
    }

    float m[8], l[8], acc0[8], acc1[8];
#pragma unroll
    for (int r = 0; r < 8; r++) { m[r] = -1e30f; l[r] = 0.0f; acc0[r] = 0.0f; acc1[r] = 0.0f; }

    const float scale = 0.125f;

    for (int kt = 0; kt < SEQ / 64; kt++) {
        __syncthreads();
        // K tile transposed: sKV[d][c]
        for (int i = tid; i < 1024; i += 256) {
            int r  = i >> 4;
            int c4 = (i & 15) * 4;
            float4 f = *(const float4*)(Kg + base + (size_t)(kt * 64 + r) * D_MODEL + c4);
            sKV[c4 + 0][r] = f.x;
            sKV[c4 + 1][r] = f.y;
            sKV[c4 + 2][r] = f.z;
            sKV[c4 + 3][r] = f.w;
        }
        __syncthreads();

        float s0[8], s1[8];
#pragma unroll
        for (int r = 0; r < 8; r++) { s0[r] = 0.0f; s1[r] = 0.0f; }
#pragma unroll 4
        for (int d4 = 0; d4 < 64; d4 += 4) {
            float k0v[4], k1v[4];
#pragma unroll
            for (int i = 0; i < 4; i++) {
                k0v[i] = sKV[d4 + i][lane];
                k1v[i] = sKV[d4 + i][lane + 32];
            }
#pragma unroll
            for (int r = 0; r < 8; r++) {
                float4 qv = *(const float4*)&sQ[warp * 8 + r][d4];
                s0[r] += qv.x * k0v[0] + qv.y * k0v[1] + qv.z * k0v[2] + qv.w * k0v[3];
                s1[r] += qv.x * k1v[0] + qv.y * k1v[1] + qv.z * k1v[2] + qv.w * k1v[3];
            }
        }

#pragma unroll
        for (int r = 0; r < 8; r++) {
            float a = s0[r] * scale;
            float c = s1[r] * scale;
            float tmax = fmaxf(a, c);
#pragma unroll
            for (int o = 16; o > 0; o >>= 1)
                tmax = fmaxf(tmax, __shfl_xor_sync(0xffffffffu, tmax, o));
            float newm = fmaxf(m[r], tmax);
            float e0 = __expf(a - newm);
            float e1 = __expf(c - newm);
            float ts = e0 + e1;
#pragma unroll
            for (int o = 16; o > 0; o >>= 1)
                ts += __shfl_xor_sync(0xffffffffu, ts, o);
            float alpha = __expf(m[r] - newm);
            l[r] = l[r] * alpha + ts;
            m[r] = newm;
            acc0[r] *= alpha;
            acc1[r] *= alpha;
            sP[warp * 8 + r][lane]      = e0;
            sP[warp * 8 + r][lane + 32] = e1;
        }
        __syncthreads();

        // V tile: sKV[c][d]
        for (int i = tid; i < 1024; i += 256) {
            int r  = i >> 4;
            int c4 = (i & 15) * 4;
            float4 f = *(const float4*)(Vg + base + (size_t)(kt * 64 + r) * D_MODEL + c4);
            *(float4*)&sKV[r][c4] = f;
        }
        __syncthreads();

#pragma unroll 4
        for (int c4 = 0; c4 < 64; c4 += 4) {
            float v0v[4], v1v[4];
#pragma unroll
            for (int i = 0; i < 4; i++) {
                v0v[i] = sKV[c4 + i][lane];
                v1v[i] = sKV[c4 + i][lane + 32];
            }
#pragma unroll
            for (int r = 0; r < 8; r++) {
                float4 p = *(const float4*)&sP[warp * 8 + r][c4];
                acc0[r] += p.x * v0v[0] + p.y * v0v[1] + p.z * v0v[2] + p.w * v0v[3];
                acc1[r] += p.x * v1v[0] + p.y * v1v[1] + p.z * v1v[2] + p.w * v1v[3];
            }
        }
    }

#pragma unroll
    for (int r = 0; r < 8; r++) {
        int row = warp * 8 + r;
        float inv = 1.0f / l[r];
        size_t o = base + (size_t)(qt * 64 + row) * D_MODEL;
        Og[o + lane]      = __uint_as_float(f2tf32(acc0[r] * inv));
        Og[o + lane + 32] = __uint_as_float(f2tf32(acc1[r] * inv));
    }
}

// ---------------------------------------------------------------------------
// LayerNorm
// ---------------------------------------------------------------------------
__global__ __launch_bounds__(256)
void ln_kernel(const float* __restrict__ X,
               const float* __restrict__ gamma,
               const float* __restrict__ beta,
               float* __restrict__ out)
{
    const int row = blockIdx.x;
    const int tid = threadIdx.x;
    const float* x = X + (size_t)row * D_MODEL;

    float4 f = *(const float4*)(x + tid * 4);
    float s  = f.x + f.y + f.z + f.w;
    float ss = f.x * f.x + f.y * f.y + f.z * f.z + f.w * f.w;

#pragma unroll
    for (int o = 16; o > 0; o >>= 1) {
        s  += __shfl_xor_sync(0xffffffffu, s,  o);
        ss += __shfl_xor_sync(0xffffffffu, ss, o);
    }

    __shared__ float sh[16];
    const int warp = tid >> 5, lane = tid & 31;
    if (lane == 0) { sh[warp] = s; sh[warp + 8] = ss; }
    __syncthreads();
    if (tid == 0) {
        float S = 0.0f, SS = 0.0f;
#pragma unroll
        for (int w = 0; w < 8; w++) { S += sh[w]; SS += sh[w + 8]; }
        float mu  = S * (1.0f / D_MODEL);
        float var = SS * (1.0f / D_MODEL) - mu * mu;
        sh[0] = mu;
        sh[1] = rsqrtf(var + LN_EPS);
    }
    __syncthreads();
    float mu = sh[0], rstd = sh[1];

    float4 gm = *(const float4*)(gamma + tid * 4);
    float4 bt = *(const float4*)(beta  + tid * 4);
    float4 o4;
    o4.x = (f.x - mu) * rstd * gm.x + bt.x;
    o4.y = (f.y - mu) * rstd * gm.y + bt.y;
    o4.z = (f.z - mu) * rstd * gm.z + bt.z;
    o4.w = (f.w - mu) * rstd * gm.w + bt.w;
    *(float4*)(out + (size_t)row * D_MODEL + tid * 4) = o4;
}

// ---------------------------------------------------------------------------
// Launch
// ---------------------------------------------------------------------------
extern "C" void kernel_launch(void* const* d_in, const int* in_sizes, int n_in,
                              void* d_out, int out_size)
{
    const float* batch = (const float*)d_in[0];
    const float* wq    = (const float*)d_in[1];
    const float* bq    = (const float*)d_in[2];
    const float* wk    = (const float*)d_in[3];
    const float* bk    = (const float*)d_in[4];
    const float* wv    = (const float*)d_in[5];
    const float* bv    = (const float*)d_in[6];
    const float* wo    = (const float*)d_in[7];
    const float* bo    = (const float*)d_in[8];
    const float* ln_g  = (const float*)d_in[9];
    const float* ln_b  = (const float*)d_in[10];

    float *q, *k, *v, *attn, *x, *bxr, *wr;
    cudaGetSymbolAddress((void**)&q,    g_q);
    cudaGetSymbolAddress((void**)&k,    g_k);
    cudaGetSymbolAddress((void**)&v,    g_v);
    cudaGetSymbolAddress((void**)&attn, g_attn);
    cudaGetSymbolAddress((void**)&x,    g_x);
    cudaGetSymbolAddress((void**)&bxr,  g_bxr);
    cudaGetSymbolAddress((void**)&wr,   g_wr);
    float* wqr = wr;
    float* wkr = wr + (size_t)D_MODEL * D_MODEL;
    float* wvr = wr + 2 * (size_t)D_MODEL * D_MODEL;
    float* wor = wr + 3 * (size_t)D_MODEL * D_MODEL;

    // tf32-round GEMM operands (rna; removes truncation bias)
    const int nb4 = MTOT * D_MODEL / 4;
    const int nw4 = D_MODEL * D_MODEL / 4;
    round_tf32_kernel<<<(nb4 + 255) / 256, 256>>>(batch, bxr, nb4);
    round_tf32_kernel<<<(nw4 + 255) / 256, 256>>>(wq, wqr, nw4);
    round_tf32_kernel<<<(nw4 + 255) / 256, 256>>>(wk, wkr, nw4);
    round_tf32_kernel<<<(nw4 + 255) / 256, 256>>>(wv, wvr, nw4);
    round_tf32_kernel<<<(nw4 + 255) / 256, 256>>>(wo, wor, nw4);

    dim3 gg(D_MODEL / 128, MTOT / 128);  // (8, 64)
    gemm_mma<false><<<gg, 256>>>(bxr, wqr, bq, nullptr, q, MTOT, D_MODEL, D_MODEL);
    gemm_mma<false><<<gg, 256>>>(bxr, wkr, bk, nullptr, k, MTOT, D_MODEL, D_MODEL);
    gemm_mma<false><<<gg, 256>>>(bxr, wvr, bv, nullptr, v, MTOT, D_MODEL, D_MODEL);

    dim3 ga(SEQ / 64, NHEAD, BATCH);
    attn_kernel<<<ga, 256>>>(q, k, v, attn);

    gemm_mma<true><<<gg, 256>>>(attn, wor, bo, batch, x, MTOT, D_MODEL, D_MODEL);

    ln_kernel<<<MTOT, 256>>>(x, ln_g, ln_b, (float*)d_out);
}

// round 4
// speedup vs baseline: 2.9585x; 2.9585x over previous
#include <cuda_runtime.h>
#include <cstdint>

#define D_MODEL 1024
#define SEQ     2048
#define BATCH   4
#define NHEAD   16
#define DHEAD   64
#define MTOT    (BATCH*SEQ)   // 8192
#define LN_EPS  1e-5f

// ---------------------------------------------------------------------------
// Scratch (no cudaMalloc allowed)
// ---------------------------------------------------------------------------
__device__ float g_q[(size_t)MTOT * D_MODEL];
__device__ float g_k[(size_t)MTOT * D_MODEL];
__device__ float g_v[(size_t)MTOT * D_MODEL];
__device__ float g_attn[(size_t)MTOT * D_MODEL];
__device__ float g_x[(size_t)MTOT * D_MODEL];
__device__ float g_bxr[(size_t)MTOT * D_MODEL];          // tf32-rounded batch
__device__ float g_wr[4][(size_t)D_MODEL * D_MODEL];     // tf32-rounded weights

// ---------------------------------------------------------------------------
// Helpers
// ---------------------------------------------------------------------------
__device__ __forceinline__ uint32_t s2u(const void* p) {
    uint32_t a;
    asm("{ .reg .u64 t; cvta.to.shared.u64 t, %1; cvt.u32.u64 %0, t; }"
        : "=r"(a) : "l"(p));
    return a;
}
__device__ __forceinline__ uint32_t f2tf32(float x) {
    uint32_t u;
    asm("cvt.rna.tf32.f32 %0, %1;" : "=r"(u) : "f"(x));
    return u;
}
__device__ __forceinline__ float f2tf32f(float x) {
    return __uint_as_float(f2tf32(x));
}

#define LDSM4(f0,f1,f2,f3,addr) \
    asm volatile("ldmatrix.sync.aligned.m8n8.x4.shared.b16 {%0,%1,%2,%3}, [%4];" \
                 : "=r"(f0), "=r"(f1), "=r"(f2), "=r"(f3) : "r"(addr))

#define MMA_TF32(d, a, b0, b1) \
    asm volatile("mma.sync.aligned.m16n8k8.row.col.f32.tf32.tf32.f32 " \
                 "{%0,%1,%2,%3}, {%4,%5,%6,%7}, {%8,%9}, {%0,%1,%2,%3};" \
                 : "+f"((d)[0]), "+f"((d)[1]), "+f"((d)[2]), "+f"((d)[3]) \
                 : "r"((a)[0]), "r"((a)[1]), "r"((a)[2]), "r"((a)[3]), \
                   "r"(b0), "r"(b1))

// ---------------------------------------------------------------------------
// Round fp32 -> tf32 (rna), elementwise
// ---------------------------------------------------------------------------
__global__ __launch_bounds__(256)
void round_tf32_kernel(const float* __restrict__ in, float* __restrict__ out, int n4)
{
    int i = blockIdx.x * blockDim.x + threadIdx.x;
    if (i < n4) {
        float4 f = ((const float4*)in)[i];
        float4 o;
        o.x = f2tf32f(f.x);
        o.y = f2tf32f(f.y);
        o.z = f2tf32f(f.z);
        o.w = f2tf32f(f.w);
        ((float4*)out)[i] = o;
    }
}

// ---------------------------------------------------------------------------
// tf32 mma.sync GEMM: C[M,N] = A[M,K] @ W[N,K]^T + bias (+resid)
// CTA tile 128x128, BK=32 chunks, NS=3-stage cp.async pipeline, 256 threads.
// Warp grid 2(m) x 4(n); warp tile 64x32. One __syncthreads per chunk.
// Smem row pitch 36 floats -> ldmatrix phases conflict-free.
// ---------------------------------------------------------------------------
#define GP    36                    // floats per smem row (32 data + 4 pad)
#define GSTG  (128 * GP * 4)        // 18432 bytes per operand per stage
#define GSM   (3 * 2 * GSTG)        // 110592 bytes dynamic smem

template<bool RESID, bool ROUND>
__global__ __launch_bounds__(256, 2)
void gemm_mma(const float* __restrict__ A, const float* __restrict__ W,
              const float* __restrict__ bias, const float* __restrict__ resid,
              float* __restrict__ C, int M, int N, int K)
{
    extern __shared__ __align__(16) char gsm[];
    const uint32_t sA = s2u(gsm);
    const uint32_t sB = sA + 3 * GSTG;

    const int tid  = threadIdx.x;
    const int wid  = tid >> 5;
    const int lane = tid & 31;
    const int wm   = wid & 1;
    const int wn   = wid >> 1;
    const int m0   = blockIdx.y * 128;
    const int n0   = blockIdx.x * 128;
    const int NCH  = K / 32;         // 32

    const int r_ld = tid >> 3;       // 0..31 base row (x4 via q)
    const int g_ld = tid & 7;        // 16B granule 0..7
    const float* Abase = A + (size_t)m0 * K + g_ld * 4;
    const float* Wbase = W + (size_t)n0 * K + g_ld * 4;

    auto issue = [&](int c) {
        if (c < NCH) {
            int st = c - (c / 3) * 3;
            uint32_t da = sA + st * GSTG;
            uint32_t db = sB + st * GSTG;
            long ko = (long)c * 32;
#pragma unroll
            for (int q = 0; q < 4; q++) {
                int row = r_ld + q * 32;
                uint32_t d  = da + row * (GP * 4) + g_ld * 16;
                const float* s = Abase + (size_t)row * K + ko;
                asm volatile("cp.async.cg.shared.global [%0], [%1], 16;"
                             :: "r"(d), "l"(s) : "memory");
                uint32_t d2 = db + row * (GP * 4) + g_ld * 16;
                const float* s2 = Wbase + (size_t)row * K + ko;
                asm volatile("cp.async.cg.shared.global [%0], [%1], 16;"
                             :: "r"(d2), "l"(s2) : "memory");
            }
        }
        asm volatile("cp.async.commit_group;" ::: "memory");
    };

    float acc[4][4][4];
#pragma unroll
    for (int i = 0; i < 4; i++)
#pragma unroll
        for (int j = 0; j < 4; j++)
#pragma unroll
            for (int k = 0; k < 4; k++) acc[i][j][k] = 0.0f;

    const int laneA_r = ((lane >> 3) & 1) * 8 + (lane & 7);
    const int laneA_g = lane >> 4;
    const int laneB_r = (lane >> 4) * 8 + (lane & 7);
    const int laneB_g = (lane >> 3) & 1;

    issue(0);
    issue(1);

    for (int c = 0; c < NCH; c++) {
        asm volatile("cp.async.wait_group 1;" ::: "memory");
        __syncthreads();
        issue(c + 2);

        int st = c - (c / 3) * 3;
        uint32_t aSt = sA + st * GSTG;
        uint32_t bSt = sB + st * GSTG;

#pragma unroll
        for (int j = 0; j < 4; j++) {          // four k8 steps
            uint32_t aF[4][4], bF[2][4];
#pragma unroll
            for (int mt = 0; mt < 4; mt++) {
                uint32_t addr = aSt + (wm * 64 + mt * 16 + laneA_r) * (GP * 4)
                                    + laneA_g * 16 + j * 32;
                LDSM4(aF[mt][0], aF[mt][1], aF[mt][2], aF[mt][3], addr);
            }
#pragma unroll
            for (int np = 0; np < 2; np++) {
                uint32_t addr = bSt + (wn * 32 + np * 16 + laneB_r) * (GP * 4)
                                    + laneB_g * 16 + j * 32;
                LDSM4(bF[np][0], bF[np][1], bF[np][2], bF[np][3], addr);
            }
#pragma unroll
            for (int mt = 0; mt < 4; mt++) {
#pragma unroll
                for (int t = 0; t < 4; t++) {
                    MMA_TF32(acc[mt][t], aF[mt],
                             bF[t >> 1][(t & 1) * 2], bF[t >> 1][(t & 1) * 2 + 1]);
                }
            }
        }
    }

    // Epilogue
    const int rb = lane >> 2;
    const int cb = (lane & 3) * 2;
#pragma unroll
    for (int mt = 0; mt < 4; mt++) {
#pragma unroll
        for (int t = 0; t < 4; t++) {
            int n = n0 + wn * 32 + t * 8 + cb;
            float2 bv = *(const float2*)(bias + n);
            int row0 = m0 + wm * 64 + mt * 16 + rb;
            int row1 = row0 + 8;
            float2 o0, o1;
            o0.x = acc[mt][t][0] + bv.x;
            o0.y = acc[mt][t][1] + bv.y;
            o1.x = acc[mt][t][2] + bv.x;
            o1.y = acc[mt][t][3] + bv.y;
            if (RESID) {
                float2 r0 = *(const float2*)(resid + (size_t)row0 * N + n);
                float2 r1 = *(const float2*)(resid + (size_t)row1 * N + n);
                o0.x += r0.x; o0.y += r0.y;
                o1.x += r1.x; o1.y += r1.y;
            }
            if (ROUND) {
                o0.x = f2tf32f(o0.x); o0.y = f2tf32f(o0.y);
                o1.x = f2tf32f(o1.x); o1.y = f2tf32f(o1.y);
            }
            *(float2*)(C + (size_t)row0 * N + n) = o0;
            *(float2*)(C + (size_t)row1 * N + n) = o1;
        }
    }
}

// ---------------------------------------------------------------------------
// Tensor-core flash attention (tf32 mma, online softmax).
// grid = (SEQ/128, NHEAD, BATCH) = (16,16,4); 256 threads = 8 warps.
// Warp w owns query rows 16w..16w+15 of the CTA's 128-row Q tile.
// K tiles of 64 keys. Q/K assumed tf32-pre-rounded (GEMM epilogue);
// P rounded to tf32 before PV; V tf32-pre-rounded.
// Smem: sK[64][68] | sVt[64][68] | sQ[128][68] | sP[128][68] = 102 KB dyn.
// ---------------------------------------------------------------------------
#define AP    68
#define APB   (AP * 4)              // 272 bytes row pitch
#define OFF_K  0
#define OFF_VT 17408
#define OFF_Q  34816
#define OFF_P  69632
#define ASM_TOTAL 104448

__global__ __launch_bounds__(256, 2)
void attn_mma(const float* __restrict__ Q,
              const float* __restrict__ Kg,
              const float* __restrict__ Vg,
              float* __restrict__ Og)
{
    extern __shared__ __align__(16) char asmem[];
    const uint32_t sb  = s2u(asmem);
    const uint32_t sK  = sb + OFF_K;
    const uint32_t sVt = sb + OFF_VT;
    const uint32_t sQ  = sb + OFF_Q;
    const uint32_t sP  = sb + OFF_P;
    float* sKf  = (float*)(asmem + OFF_K);
    float* sVtf = (float*)(asmem + OFF_VT);
    float* sQf  = (float*)(asmem + OFF_Q);
    float* sPf  = (float*)(asmem + OFF_P);

    const int qt   = blockIdx.x;
    const int h    = blockIdx.y;
    const int b    = blockIdx.z;
    const int tid  = threadIdx.x;
    const int warp = tid >> 5;
    const int lane = tid & 31;

    const size_t base = ((size_t)b * SEQ) * D_MODEL + (size_t)h * DHEAD;

    // Load Q tile (128 x 64) into sQ
    for (int i = tid; i < 2048; i += 256) {
        int r  = i >> 4;
        int c4 = (i & 15) * 4;
        float4 f = *(const float4*)(Q + base + (size_t)(qt * 128 + r) * D_MODEL + c4);
        *(float4*)(sQf + r * AP + c4) = f;
    }

    const int laneA_r = ((lane >> 3) & 1) * 8 + (lane & 7);
    const int laneA_g = lane >> 4;
    const int laneB_r = (lane >> 4) * 8 + (lane & 7);
    const int laneB_g = (lane >> 3) & 1;

    float m0 = -1e30f, m1 = -1e30f, l0 = 0.0f, l1 = 0.0f;
    float o[8][4];
#pragma unroll
    for (int nt = 0; nt < 8; nt++)
#pragma unroll
        for (int i = 0; i < 4; i++) o[nt][i] = 0.0f;

    __syncthreads();

    for (int kt = 0; kt < SEQ / 64; kt++) {
        // Load K tile [64 keys][64 d] straight; V transposed into sVt[d][key]
        const size_t kbase = base + (size_t)(kt * 64) * D_MODEL;
        for (int i = tid; i < 1024; i += 256) {
            int r  = i >> 4;
            int c4 = (i & 15) * 4;
            float4 f = *(const float4*)(Kg + kbase + (size_t)r * D_MODEL + c4);
            *(float4*)(sKf + r * AP + c4) = f;
            float4 g = *(const float4*)(Vg + kbase + (size_t)r * D_MODEL + c4);
            sVtf[(c4 + 0) * AP + r] = g.x;
            sVtf[(c4 + 1) * AP + r] = g.y;
            sVtf[(c4 + 2) * AP + r] = g.z;
            sVtf[(c4 + 3) * AP + r] = g.w;
        }
        __syncthreads();

        // S = Q @ K^T  (8 k-steps over d, 8 n-tiles over 64 keys)
        float s[8][4];
#pragma unroll
        for (int nt = 0; nt < 8; nt++)
#pragma unroll
            for (int i = 0; i < 4; i++) s[nt][i] = 0.0f;

#pragma unroll
        for (int j = 0; j < 8; j++) {
            uint32_t aF[4];
            LDSM4(aF[0], aF[1], aF[2], aF[3],
                  sQ + (warp * 16 + laneA_r) * APB + (laneA_g + 2 * j) * 16);
            uint32_t bF[4][4];
#pragma unroll
            for (int np = 0; np < 4; np++) {
                LDSM4(bF[np][0], bF[np][1], bF[np][2], bF[np][3],
                      sK + (np * 16 + laneB_r) * APB + (laneB_g + 2 * j) * 16);
            }
#pragma unroll
            for (int nt = 0; nt < 8; nt++)
                MMA_TF32(s[nt], aF, bF[nt >> 1][(nt & 1) * 2], bF[nt >> 1][(nt & 1) * 2 + 1]);
        }

        // scale + online softmax (rows r0=lane>>2 and r0+8 of this warp's m16)
        float mx0 = -1e30f, mx1 = -1e30f;
#pragma unroll
        for (int nt = 0; nt < 8; nt++) {
            s[nt][0] *= 0.125f; s[nt][1] *= 0.125f;
            s[nt][2] *= 0.125f; s[nt][3] *= 0.125f;
            mx0 = fmaxf(mx0, fmaxf(s[nt][0], s[nt][1]));
            mx1 = fmaxf(mx1, fmaxf(s[nt][2], s[nt][3]));
        }
        mx0 = fmaxf(mx0, __shfl_xor_sync(0xffffffffu, mx0, 1));
        mx0 = fmaxf(mx0, __shfl_xor_sync(0xffffffffu, mx0, 2));
        mx1 = fmaxf(mx1, __shfl_xor_sync(0xffffffffu, mx1, 1));
        mx1 = fmaxf(mx1, __shfl_xor_sync(0xffffffffu, mx1, 2));
        float nm0 = fmaxf(m0, mx0), nm1 = fmaxf(m1, mx1);
        float a0 = __expf(m0 - nm0), a1 = __expf(m1 - nm1);

        float sum0 = 0.0f, sum1 = 0.0f;
#pragma unroll
        for (int nt = 0; nt < 8; nt++) {
            s[nt][0] = f2tf32f(__expf(s[nt][0] - nm0));
            s[nt][1] = f2tf32f(__expf(s[nt][1] - nm0));
            s[nt][2] = f2tf32f(__expf(s[nt][2] - nm1));
            s[nt][3] = f2tf32f(__expf(s[nt][3] - nm1));
            sum0 += s[nt][0] + s[nt][1];
            sum1 += s[nt][2] + s[nt][3];
        }
        sum0 += __shfl_xor_sync(0xffffffffu, sum0, 1);
        sum0 += __shfl_xor_sync(0xffffffffu, sum0, 2);
        sum1 += __shfl_xor_sync(0xffffffffu, sum1, 1);
        sum1 += __shfl_xor_sync(0xffffffffu, sum1, 2);
        l0 = l0 * a0 + sum0;
        l1 = l1 * a1 + sum1;
        m0 = nm0; m1 = nm1;
#pragma unroll
        for (int nt = 0; nt < 8; nt++) {
            o[nt][0] *= a0; o[nt][1] *= a0;
            o[nt][2] *= a1; o[nt][3] *= a1;
        }

        // Write P to this warp's private rows of sP
        {
            int r0 = warp * 16 + (lane >> 2);
            int c0 = (lane & 3) * 2;
#pragma unroll
            for (int nt = 0; nt < 8; nt++) {
                *(float2*)(sPf + r0 * AP + nt * 8 + c0)       = make_float2(s[nt][0], s[nt][1]);
                *(float2*)(sPf + (r0 + 8) * AP + nt * 8 + c0) = make_float2(s[nt][2], s[nt][3]);
            }
        }
        __syncwarp();

        // O += P @ V  (8 k-steps over 64 keys, 8 n-tiles over d)
#pragma unroll
        for (int j = 0; j < 8; j++) {
            uint32_t aF[4];
            LDSM4(aF[0], aF[1], aF[2], aF[3],
                  sP + (warp * 16 + laneA_r) * APB + (laneA_g + 2 * j) * 16);
            uint32_t bF[4][4];
#pragma unroll
            for (int np = 0; np < 4; np++) {
                LDSM4(bF[np][0], bF[np][1], bF[np][2], bF[np][3],
                      sVt + (np * 16 + laneB_r) * APB + (laneB_g + 2 * j) * 16);
            }
#pragma unroll
            for (int nt = 0; nt < 8; nt++)
                MMA_TF32(o[nt], aF, bF[nt >> 1][(nt & 1) * 2], bF[nt >> 1][(nt & 1) * 2 + 1]);
        }
        __syncthreads();   // before next kt overwrites sK/sVt
    }

    // Epilogue: normalize + tf32-round (feeds tf32 out-proj GEMM)
    float inv0 = 1.0f / l0, inv1 = 1.0f / l1;
    int r0 = qt * 128 + warp * 16 + (lane >> 2);
    int c0 = (lane & 3) * 2;
#pragma unroll
    for (int nt = 0; nt < 8; nt++) {
        size_t p0 = base + (size_t)r0 * D_MODEL + nt * 8 + c0;
        size_t p1 = base + (size_t)(r0 + 8) * D_MODEL + nt * 8 + c0;
        *(float2*)(Og + p0) = make_float2(f2tf32f(o[nt][0] * inv0), f2tf32f(o[nt][1] * inv0));
        *(float2*)(Og + p1) = make_float2(f2tf32f(o[nt][2] * inv1), f2tf32f(o[nt][3] * inv1));
    }
}

// ---------------------------------------------------------------------------
// LayerNorm
// ---------------------------------------------------------------------------
__global__ __launch_bounds__(256)
void ln_kernel(const float* __restrict__ X,
               const float* __restrict__ gamma,
               const float* __restrict__ beta,
               float* __restrict__ out)
{
    const int row = blockIdx.x;
    const int tid = threadIdx.x;
    const float* x = X + (size_t)row * D_MODEL;

    float4 f = *(const float4*)(x + tid * 4);
    float s  = f.x + f.y + f.z + f.w;
    float ss = f.x * f.x + f.y * f.y + f.z * f.z + f.w * f.w;

#pragma unroll
    for (int o = 16; o > 0; o >>= 1) {
        s  += __shfl_xor_sync(0xffffffffu, s,  o);
        ss += __shfl_xor_sync(0xffffffffu, ss, o);
    }

    __shared__ float sh[16];
    const int warp = tid >> 5, lane = tid & 31;
    if (lane == 0) { sh[warp] = s; sh[warp + 8] = ss; }
    __syncthreads();
    if (tid == 0) {
        float S = 0.0f, SS = 0.0f;
#pragma unroll
        for (int w = 0; w < 8; w++) { S += sh[w]; SS += sh[w + 8]; }
        float mu  = S * (1.0f / D_MODEL);
        float var = SS * (1.0f / D_MODEL) - mu * mu;
        sh[0] = mu;
        sh[1] = rsqrtf(var + LN_EPS);
    }
    __syncthreads();
    float mu = sh[0], rstd = sh[1];

    float4 gm = *(const float4*)(gamma + tid * 4);
    float4 bt = *(const float4*)(beta  + tid * 4);
    float4 o4;
    o4.x = (f.x - mu) * rstd * gm.x + bt.x;
    o4.y = (f.y - mu) * rstd * gm.y + bt.y;
    o4.z = (f.z - mu) * rstd * gm.z + bt.z;
    o4.w = (f.w - mu) * rstd * gm.w + bt.w;
    *(float4*)(out + (size_t)row * D_MODEL + tid * 4) = o4;
}

// ---------------------------------------------------------------------------
// Launch
// ---------------------------------------------------------------------------
extern "C" void kernel_launch(void* const* d_in, const int* in_sizes, int n_in,
                              void* d_out, int out_size)
{
    const float* batch = (const float*)d_in[0];
    const float* wq    = (const float*)d_in[1];
    const float* bq    = (const float*)d_in[2];
    const float* wk    = (const float*)d_in[3];
    const float* bk    = (const float*)d_in[4];
    const float* wv    = (const float*)d_in[5];
    const float* bv    = (const float*)d_in[6];
    const float* wo    = (const float*)d_in[7];
    const float* bo    = (const float*)d_in[8];
    const float* ln_g  = (const float*)d_in[9];
    const float* ln_b  = (const float*)d_in[10];

    float *q, *k, *v, *attn, *x, *bxr, *wr;
    cudaGetSymbolAddress((void**)&q,    g_q);
    cudaGetSymbolAddress((void**)&k,    g_k);
    cudaGetSymbolAddress((void**)&v,    g_v);
    cudaGetSymbolAddress((void**)&attn, g_attn);
    cudaGetSymbolAddress((void**)&x,    g_x);
    cudaGetSymbolAddress((void**)&bxr,  g_bxr);
    cudaGetSymbolAddress((void**)&wr,   g_wr);
    float* wqr = wr;
    float* wkr = wr + (size_t)D_MODEL * D_MODEL;
    float* wvr = wr + 2 * (size_t)D_MODEL * D_MODEL;
    float* wor = wr + 3 * (size_t)D_MODEL * D_MODEL;

    static bool attr_done = false;
    if (!attr_done) {
        cudaFuncSetAttribute(gemm_mma<false, true>,
                             cudaFuncAttributeMaxDynamicSharedMemorySize, GSM);
        cudaFuncSetAttribute(gemm_mma<true, false>,
                             cudaFuncAttributeMaxDynamicSharedMemorySize, GSM);
        cudaFuncSetAttribute(attn_mma,
                             cudaFuncAttributeMaxDynamicSharedMemorySize, ASM_TOTAL);
        attr_done = true;
    }

    // tf32-round GEMM operands (rna; removes truncation bias)
    const int nb4 = MTOT * D_MODEL / 4;
    const int nw4 = D_MODEL * D_MODEL / 4;
    round_tf32_kernel<<<(nb4 + 255) / 256, 256>>>(batch, bxr, nb4);
    round_tf32_kernel<<<(nw4 + 255) / 256, 256>>>(wq, wqr, nw4);
    round_tf32_kernel<<<(nw4 + 255) / 256, 256>>>(wk, wkr, nw4);
    round_tf32_kernel<<<(nw4 + 255) / 256, 256>>>(wv, wvr, nw4);
    round_tf32_kernel<<<(nw4 + 255) / 256, 256>>>(wo, wor, nw4);

    dim3 gg(D_MODEL / 128, MTOT / 128);  // (8, 64)
    gemm_mma<false, true><<<gg, 256, GSM>>>(bxr, wqr, bq, nullptr, q, MTOT, D_MODEL, D_MODEL);
    gemm_mma<false, true><<<gg, 256, GSM>>>(bxr, wkr, bk, nullptr, k, MTOT, D_MODEL, D_MODEL);
    gemm_mma<false, true><<<gg, 256, GSM>>>(bxr, wvr, bv, nullptr, v, MTOT, D_MODEL, D_MODEL);

    dim3 ga(SEQ / 128, NHEAD, BATCH);    // (16, 16, 4)
    attn_mma<<<ga, 256, ASM_TOTAL>>>(q, k, v, attn);

    gemm_mma<true, false><<<gg, 256, GSM>>>(attn, wor, bo, batch, x, MTOT, D_MODEL, D_MODEL);

    ln_kernel<<<MTOT, 256>>>(x, ln_g, ln_b, (float*)d_out);
}

// round 5
// speedup vs baseline: 7.3042x; 2.4689x over previous
#include <cuda_runtime.h>
#include <cuda_bf16.h>
#include <cstdint>

#define D_MODEL 1024
#define SEQ     2048
#define BATCH   4
#define NHEAD   16
#define DHEAD   64
#define MTOT    (BATCH*SEQ)   // 8192
#define LN_EPS  1e-5f

// ---------------------------------------------------------------------------
// Scratch (no cudaMalloc allowed). bf16 operands, fp32 where accuracy matters.
// ---------------------------------------------------------------------------
__device__ __nv_bfloat16 g_qh[(size_t)MTOT * D_MODEL];
__device__ __nv_bfloat16 g_kh[(size_t)MTOT * D_MODEL];
__device__ __nv_bfloat16 g_vh[(size_t)MTOT * D_MODEL];
__device__ __nv_bfloat16 g_ah[(size_t)MTOT * D_MODEL];   // attention output
__device__ __nv_bfloat16 g_bxh[(size_t)MTOT * D_MODEL];  // bf16 batch
__device__ __nv_bfloat16 g_wh[4][(size_t)D_MODEL * D_MODEL];
__device__ float g_x[(size_t)MTOT * D_MODEL];            // residual sum (fp32)

// ---------------------------------------------------------------------------
// Helpers
// ---------------------------------------------------------------------------
__device__ __forceinline__ uint32_t s2u(const void* p) {
    uint32_t a;
    asm("{ .reg .u64 t; cvta.to.shared.u64 t, %1; cvt.u32.u64 %0, t; }"
        : "=r"(a) : "l"(p));
    return a;
}

#define LDSM4(f0,f1,f2,f3,addr) \
    asm volatile("ldmatrix.sync.aligned.m8n8.x4.shared.b16 {%0,%1,%2,%3}, [%4];" \
                 : "=r"(f0), "=r"(f1), "=r"(f2), "=r"(f3) : "r"(addr))

#define MMA_BF16(d, a, b0, b1) \
    asm volatile("mma.sync.aligned.m16n8k16.row.col.f32.bf16.bf16.f32 " \
                 "{%0,%1,%2,%3}, {%4,%5,%6,%7}, {%8,%9}, {%0,%1,%2,%3};" \
                 : "+f"((d)[0]), "+f"((d)[1]), "+f"((d)[2]), "+f"((d)[3]) \
                 : "r"((a)[0]), "r"((a)[1]), "r"((a)[2]), "r"((a)[3]), \
                   "r"(b0), "r"(b1))

// ---------------------------------------------------------------------------
// fp32 -> bf16 (rn) conversion
// ---------------------------------------------------------------------------
__global__ __launch_bounds__(256)
void conv_bf16_kernel(const float* __restrict__ in, __nv_bfloat16* __restrict__ out, int n4)
{
    int i = blockIdx.x * blockDim.x + threadIdx.x;
    if (i < n4) {
        float4 f = ((const float4*)in)[i];
        ((__nv_bfloat162*)out)[i * 2]     = __floats2bfloat162_rn(f.x, f.y);
        ((__nv_bfloat162*)out)[i * 2 + 1] = __floats2bfloat162_rn(f.z, f.w);
    }
}

// ---------------------------------------------------------------------------
// bf16 mma GEMM: C[M,N] = A[M,K] @ W[N,K]^T + bias (+resid fp32)
// CTA 128x128, BK=32 halves, NS=4 cp.async stages, 256 threads (8 warps).
// Warp grid 2(m) x 4(n); warp tile 64x32.
// Smem row pitch 40 halves (80B): 8-row ldmatrix phases conflict-free.
// OUT_BF16: write bf16 (QKV path); else fp32 (+resid).
// ---------------------------------------------------------------------------
#define GPH   40                    // halves per smem row (32 data + 8 pad)
#define GSTGB (128 * GPH * 2)       // 10240 bytes per operand per stage
#define GSM   (4 * 2 * GSTGB)       // 81920 bytes dynamic smem

template<bool OUT_BF16, bool RESID>
__global__ __launch_bounds__(256, 2)
void gemm_bf16(const __nv_bfloat16* __restrict__ A, const __nv_bfloat16* __restrict__ W,
               const float* __restrict__ bias, const float* __restrict__ resid,
               void* __restrict__ Cv, int M, int N, int K)
{
    extern __shared__ __align__(16) char gsm[];
    const uint32_t sA = s2u(gsm);
    const uint32_t sB = sA + 4 * GSTGB;

    const int tid  = threadIdx.x;
    const int wid  = tid >> 5;
    const int lane = tid & 31;
    const int wm   = wid & 1;
    const int wn   = wid >> 1;
    const int m0   = blockIdx.y * 128;
    const int n0   = blockIdx.x * 128;
    const int NCH  = K / 32;         // 32

    const int r_ld = tid >> 2;       // 0..63 base row
    const int g_ld = tid & 3;        // 16B granule (8 halves)
    const __nv_bfloat16* Abase = A + (size_t)m0 * K + g_ld * 8;
    const __nv_bfloat16* Wbase = W + (size_t)n0 * K + g_ld * 8;

    auto issue = [&](int c) {
        if (c < NCH) {
            int st = c & 3;
            uint32_t da = sA + st * GSTGB;
            uint32_t db = sB + st * GSTGB;
            long ko = (long)c * 32;
#pragma unroll
            for (int q = 0; q < 2; q++) {
                int row = r_ld + q * 64;
                uint32_t d  = da + row * (GPH * 2) + g_ld * 16;
                const __nv_bfloat16* s = Abase + (size_t)row * K + ko;
                asm volatile("cp.async.cg.shared.global [%0], [%1], 16;"
                             :: "r"(d), "l"(s) : "memory");
                uint32_t d2 = db + row * (GPH * 2) + g_ld * 16;
                const __nv_bfloat16* s2 = Wbase + (size_t)row * K + ko;
                asm volatile("cp.async.cg.shared.global [%0], [%1], 16;"
                             :: "r"(d2), "l"(s2) : "memory");
            }
        }
        asm volatile("cp.async.commit_group;" ::: "memory");
    };

    float acc[4][4][4];
#pragma unroll
    for (int i = 0; i < 4; i++)
#pragma unroll
        for (int j = 0; j < 4; j++)
#pragma unroll
            for (int k = 0; k < 4; k++) acc[i][j][k] = 0.0f;

    const int laneA_r = ((lane >> 3) & 1) * 8 + (lane & 7);
    const int laneA_g = lane >> 4;
    const int laneB_r = (lane >> 4) * 8 + (lane & 7);
    const int laneB_g = (lane >> 3) & 1;

    issue(0); issue(1); issue(2);

    for (int c = 0; c < NCH; c++) {
        asm volatile("cp.async.wait_group 2;" ::: "memory");
        __syncthreads();
        issue(c + 3);

        int st = c & 3;
        uint32_t aSt = sA + st * GSTGB;
        uint32_t bSt = sB + st * GSTGB;

#pragma unroll
        for (int j = 0; j < 2; j++) {          // two k16 steps per BK=32
            uint32_t aF[4][4], bF[2][4];
#pragma unroll
            for (int mt = 0; mt < 4; mt++) {
                uint32_t addr = aSt + (wm * 64 + mt * 16 + laneA_r) * (GPH * 2)
                                    + (laneA_g + 2 * j) * 16;
                LDSM4(aF[mt][0], aF[mt][1], aF[mt][2], aF[mt][3], addr);
            }
#pragma unroll
            for (int np = 0; np < 2; np++) {
                uint32_t addr = bSt + (wn * 32 + np * 16 + laneB_r) * (GPH * 2)
                                    + (laneB_g + 2 * j) * 16;
                LDSM4(bF[np][0], bF[np][1], bF[np][2], bF[np][3], addr);
            }
#pragma unroll
            for (int mt = 0; mt < 4; mt++) {
#pragma unroll
                for (int t = 0; t < 4; t++) {
                    MMA_BF16(acc[mt][t], aF[mt],
                             bF[t >> 1][(t & 1) * 2], bF[t >> 1][(t & 1) * 2 + 1]);
                }
            }
        }
    }

    // Epilogue
    const int rb = lane >> 2;
    const int cb = (lane & 3) * 2;
#pragma unroll
    for (int mt = 0; mt < 4; mt++) {
#pragma unroll
        for (int t = 0; t < 4; t++) {
            int n = n0 + wn * 32 + t * 8 + cb;
            float2 bv = *(const float2*)(bias + n);
            int row0 = m0 + wm * 64 + mt * 16 + rb;
            int row1 = row0 + 8;
            float v00 = acc[mt][t][0] + bv.x;
            float v01 = acc[mt][t][1] + bv.y;
            float v10 = acc[mt][t][2] + bv.x;
            float v11 = acc[mt][t][3] + bv.y;
            if (OUT_BF16) {
                __nv_bfloat16* C = (__nv_bfloat16*)Cv;
                *(__nv_bfloat162*)(C + (size_t)row0 * N + n) = __floats2bfloat162_rn(v00, v01);
                *(__nv_bfloat162*)(C + (size_t)row1 * N + n) = __floats2bfloat162_rn(v10, v11);
            } else {
                float* C = (float*)Cv;
                if (RESID) {
                    float2 r0 = *(const float2*)(resid + (size_t)row0 * N + n);
                    float2 r1 = *(const float2*)(resid + (size_t)row1 * N + n);
                    v00 += r0.x; v01 += r0.y;
                    v10 += r1.x; v11 += r1.y;
                }
                *(float2*)(C + (size_t)row0 * N + n) = make_float2(v00, v01);
                *(float2*)(C + (size_t)row1 * N + n) = make_float2(v10, v11);
            }
        }
    }
}

// ---------------------------------------------------------------------------
// bf16 tensor-core flash attention (fp32 accum + softmax).
// grid = (SEQ/128, NHEAD, BATCH) = (16,16,4); 256 threads = 8 warps.
// Warp w owns query rows 16w..16w+15. K tiles of 64 keys.
// Smem (bf16, pitch 72 halves = 144B, conflict-free ldmatrix phases):
//   sK 64x72 (9216B) | sVt 64x72 (9216B) | sQ 128x72 (18432B) | sP 128x72 (18432B)
// ---------------------------------------------------------------------------
#define APH    72
#define APB    (APH * 2)            // 144 bytes row pitch
#define OFF_K  0
#define OFF_VT 9216
#define OFF_Q  18432
#define OFF_P  36864
#define ASM_TOTAL 55296

__global__ __launch_bounds__(256, 2)
void attn_bf16(const __nv_bfloat16* __restrict__ Q,
               const __nv_bfloat16* __restrict__ Kg,
               const __nv_bfloat16* __restrict__ Vg,
               __nv_bfloat16* __restrict__ Og)
{
    extern __shared__ __align__(16) char asmem[];
    const uint32_t sb  = s2u(asmem);
    const uint32_t sK  = sb + OFF_K;
    const uint32_t sVt = sb + OFF_VT;
    const uint32_t sQ  = sb + OFF_Q;
    const uint32_t sP  = sb + OFF_P;
    __nv_bfloat16* smK  = (__nv_bfloat16*)(asmem + OFF_K);
    __nv_bfloat16* smVt = (__nv_bfloat16*)(asmem + OFF_VT);
    __nv_bfloat16* smQ  = (__nv_bfloat16*)(asmem + OFF_Q);
    __nv_bfloat16* smP  = (__nv_bfloat16*)(asmem + OFF_P);

    const int qt   = blockIdx.x;
    const int h    = blockIdx.y;
    const int b    = blockIdx.z;
    const int tid  = threadIdx.x;
    const int warp = tid >> 5;
    const int lane = tid & 31;

    const size_t base = ((size_t)b * SEQ) * D_MODEL + (size_t)h * DHEAD;

    // Load Q tile (128 x 64 halves): 1024 16B-granules, 4 per thread
    for (int i = tid; i < 1024; i += 256) {
        int r = i >> 3;
        int g = i & 7;
        uint4 f = *(const uint4*)(Q + base + (size_t)(qt * 128 + r) * D_MODEL + g * 8);
        *(uint4*)(smQ + r * APH + g * 8) = f;
    }

    const int laneA_r = ((lane >> 3) & 1) * 8 + (lane & 7);
    const int laneA_g = lane >> 4;
    const int laneB_r = (lane >> 4) * 8 + (lane & 7);
    const int laneB_g = (lane >> 3) & 1;

    float m0 = -1e30f, m1 = -1e30f, l0 = 0.0f, l1 = 0.0f;
    float o[8][4];
#pragma unroll
    for (int nt = 0; nt < 8; nt++)
#pragma unroll
        for (int i = 0; i < 4; i++) o[nt][i] = 0.0f;

    __syncthreads();

    for (int kt = 0; kt < SEQ / 64; kt++) {
        const size_t kbase = base + (size_t)(kt * 64) * D_MODEL;
        // K straight [key][d]; V transposed [d][key]
        for (int i = tid; i < 512; i += 256) {
            int r = i >> 3;
            int g = i & 7;
            uint4 f = *(const uint4*)(Kg + kbase + (size_t)r * D_MODEL + g * 8);
            *(uint4*)(smK + r * APH + g * 8) = f;
            uint4 vv = *(const uint4*)(Vg + kbase + (size_t)r * D_MODEL + g * 8);
            const __nv_bfloat16* vh = (const __nv_bfloat16*)&vv;
#pragma unroll
            for (int t = 0; t < 8; t++)
                smVt[(g * 8 + t) * APH + r] = vh[t];
        }
        __syncthreads();

        // S = Q @ K^T  (4 k16 steps over d=64; 8 n8-tiles over 64 keys)
        float s[8][4];
#pragma unroll
        for (int nt = 0; nt < 8; nt++)
#pragma unroll
            for (int i = 0; i < 4; i++) s[nt][i] = 0.0f;

#pragma unroll
        for (int j = 0; j < 4; j++) {
            uint32_t aF[4];
            LDSM4(aF[0], aF[1], aF[2], aF[3],
                  sQ + (warp * 16 + laneA_r) * APB + (laneA_g + 2 * j) * 16);
            uint32_t bF[4][4];
#pragma unroll
            for (int np = 0; np < 4; np++) {
                LDSM4(bF[np][0], bF[np][1], bF[np][2], bF[np][3],
                      sK + (np * 16 + laneB_r) * APB + (laneB_g + 2 * j) * 16);
            }
#pragma unroll
            for (int nt = 0; nt < 8; nt++)
                MMA_BF16(s[nt], aF, bF[nt >> 1][(nt & 1) * 2], bF[nt >> 1][(nt & 1) * 2 + 1]);
        }

        // scale + online softmax (rows r0 and r0+8 of warp's m16)
        float mx0 = -1e30f, mx1 = -1e30f;
#pragma unroll
        for (int nt = 0; nt < 8; nt++) {
            s[nt][0] *= 0.125f; s[nt][1] *= 0.125f;
            s[nt][2] *= 0.125f; s[nt][3] *= 0.125f;
            mx0 = fmaxf(mx0, fmaxf(s[nt][0], s[nt][1]));
            mx1 = fmaxf(mx1, fmaxf(s[nt][2], s[nt][3]));
        }
        mx0 = fmaxf(mx0, __shfl_xor_sync(0xffffffffu, mx0, 1));
        mx0 = fmaxf(mx0, __shfl_xor_sync(0xffffffffu, mx0, 2));
        mx1 = fmaxf(mx1, __shfl_xor_sync(0xffffffffu, mx1, 1));
        mx1 = fmaxf(mx1, __shfl_xor_sync(0xffffffffu, mx1, 2));
        float nm0 = fmaxf(m0, mx0), nm1 = fmaxf(m1, mx1);
        float a0 = __expf(m0 - nm0), a1 = __expf(m1 - nm1);

        float sum0 = 0.0f, sum1 = 0.0f;
        int r0 = warp * 16 + (lane >> 2);
        int c0 = (lane & 3) * 2;
#pragma unroll
        for (int nt = 0; nt < 8; nt++) {
            float e00 = __expf(s[nt][0] - nm0);
            float e01 = __expf(s[nt][1] - nm0);
            float e10 = __expf(s[nt][2] - nm1);
            float e11 = __expf(s[nt][3] - nm1);
            sum0 += e00 + e01;
            sum1 += e10 + e11;
            *(__nv_bfloat162*)(smP + r0 * APH + nt * 8 + c0)       = __floats2bfloat162_rn(e00, e01);
            *(__nv_bfloat162*)(smP + (r0 + 8) * APH + nt * 8 + c0) = __floats2bfloat162_rn(e10, e11);
        }
        sum0 += __shfl_xor_sync(0xffffffffu, sum0, 1);
        sum0 += __shfl_xor_sync(0xffffffffu, sum0, 2);
        sum1 += __shfl_xor_sync(0xffffffffu, sum1, 1);
        sum1 += __shfl_xor_sync(0xffffffffu, sum1, 2);
        l0 = l0 * a0 + sum0;
        l1 = l1 * a1 + sum1;
        m0 = nm0; m1 = nm1;
#pragma unroll
        for (int nt = 0; nt < 8; nt++) {
            o[nt][0] *= a0; o[nt][1] *= a0;
            o[nt][2] *= a1; o[nt][3] *= a1;
        }
        __syncwarp();

        // O += P @ V  (4 k16 steps over 64 keys; 8 n8-tiles over d=64)
#pragma unroll
        for (int j = 0; j < 4; j++) {
            uint32_t aF[4];
            LDSM4(aF[0], aF[1], aF[2], aF[3],
                  sP + (warp * 16 + laneA_r) * APB + (laneA_g + 2 * j) * 16);
            uint32_t bF[4][4];
#pragma unroll
            for (int np = 0; np < 4; np++) {
                LDSM4(bF[np][0], bF[np][1], bF[np][2], bF[np][3],
                      sVt + (np * 16 + laneB_r) * APB + (laneB_g + 2 * j) * 16);
            }
#pragma unroll
            for (int nt = 0; nt < 8; nt++)
                MMA_BF16(o[nt], aF, bF[nt >> 1][(nt & 1) * 2], bF[nt >> 1][(nt & 1) * 2 + 1]);
        }
        __syncthreads();   // before next kt overwrites sK/sVt
    }

    // Epilogue: normalize, convert bf16
    float inv0 = 1.0f / l0, inv1 = 1.0f / l1;
    int r0 = qt * 128 + warp * 16 + (lane >> 2);
    int c0 = (lane & 3) * 2;
#pragma unroll
    for (int nt = 0; nt < 8; nt++) {
        size_t p0 = base + (size_t)r0 * D_MODEL + nt * 8 + c0;
        size_t p1 = base + (size_t)(r0 + 8) * D_MODEL + nt * 8 + c0;
        *(__nv_bfloat162*)(Og + p0) = __floats2bfloat162_rn(o[nt][0] * inv0, o[nt][1] * inv0);
        *(__nv_bfloat162*)(Og + p1) = __floats2bfloat162_rn(o[nt][2] * inv1, o[nt][3] * inv1);
    }
}

// ---------------------------------------------------------------------------
// LayerNorm
// ---------------------------------------------------------------------------
__global__ __launch_bounds__(256)
void ln_kernel(const float* __restrict__ X,
               const float* __restrict__ gamma,
               const float* __restrict__ beta,
               float* __restrict__ out)
{
    const int row = blockIdx.x;
    const int tid = threadIdx.x;
    const float* x = X + (size_t)row * D_MODEL;

    float4 f = *(const float4*)(x + tid * 4);
    float s  = f.x + f.y + f.z + f.w;
    float ss = f.x * f.x + f.y * f.y + f.z * f.z + f.w * f.w;

#pragma unroll
    for (int o = 16; o > 0; o >>= 1) {
        s  += __shfl_xor_sync(0xffffffffu, s,  o);
        ss += __shfl_xor_sync(0xffffffffu, ss, o);
    }

    __shared__ float sh[16];
    const int warp = tid >> 5, lane = tid & 31;
    if (lane == 0) { sh[warp] = s; sh[warp + 8] = ss; }
    __syncthreads();
    if (tid == 0) {
        float S = 0.0f, SS = 0.0f;
#pragma unroll
        for (int w = 0; w < 8; w++) { S += sh[w]; SS += sh[w + 8]; }
        float mu  = S * (1.0f / D_MODEL);
        float var = SS * (1.0f / D_MODEL) - mu * mu;
        sh[0] = mu;
        sh[1] = rsqrtf(var + LN_EPS);
    }
    __syncthreads();
    float mu = sh[0], rstd = sh[1];

    float4 gm = *(const float4*)(gamma + tid * 4);
    float4 bt = *(const float4*)(beta  + tid * 4);
    float4 o4;
    o4.x = (f.x - mu) * rstd * gm.x + bt.x;
    o4.y = (f.y - mu) * rstd * gm.y + bt.y;
    o4.z = (f.z - mu) * rstd * gm.z + bt.z;
    o4.w = (f.w - mu) * rstd * gm.w + bt.w;
    *(float4*)(out + (size_t)row * D_MODEL + tid * 4) = o4;
}

// ---------------------------------------------------------------------------
// Launch
// ---------------------------------------------------------------------------
extern "C" void kernel_launch(void* const* d_in, const int* in_sizes, int n_in,
                              void* d_out, int out_size)
{
    const float* batch = (const float*)d_in[0];
    const float* wq    = (const float*)d_in[1];
    const float* bq    = (const float*)d_in[2];
    const float* wk    = (const float*)d_in[3];
    const float* bk    = (const float*)d_in[4];
    const float* wv    = (const float*)d_in[5];
    const float* bv    = (const float*)d_in[6];
    const float* wo    = (const float*)d_in[7];
    const float* bo    = (const float*)d_in[8];
    const float* ln_g  = (const float*)d_in[9];
    const float* ln_b  = (const float*)d_in[10];

    __nv_bfloat16 *qh, *kh, *vh, *ah, *bxh, *wh;
    float *x;
    cudaGetSymbolAddress((void**)&qh,  g_qh);
    cudaGetSymbolAddress((void**)&kh,  g_kh);
    cudaGetSymbolAddress((void**)&vh,  g_vh);
    cudaGetSymbolAddress((void**)&ah,  g_ah);
    cudaGetSymbolAddress((void**)&bxh, g_bxh);
    cudaGetSymbolAddress((void**)&wh,  g_wh);
    cudaGetSymbolAddress((void**)&x,   g_x);
    __nv_bfloat16* wqh = wh;
    __nv_bfloat16* wkh = wh + (size_t)D_MODEL * D_MODEL;
    __nv_bfloat16* wvh = wh + 2 * (size_t)D_MODEL * D_MODEL;
    __nv_bfloat16* woh = wh + 3 * (size_t)D_MODEL * D_MODEL;

    static bool attr_done = false;
    if (!attr_done) {
        cudaFuncSetAttribute(gemm_bf16<true, false>,
                             cudaFuncAttributeMaxDynamicSharedMemorySize, GSM);
        cudaFuncSetAttribute(gemm_bf16<false, true>,
                             cudaFuncAttributeMaxDynamicSharedMemorySize, GSM);
        cudaFuncSetAttribute(attn_bf16,
                             cudaFuncAttributeMaxDynamicSharedMemorySize, ASM_TOTAL);
        attr_done = true;
    }

    // fp32 -> bf16 (rn) conversions
    const int nb4 = MTOT * D_MODEL / 4;
    const int nw4 = D_MODEL * D_MODEL / 4;
    conv_bf16_kernel<<<(nb4 + 255) / 256, 256>>>(batch, bxh, nb4);
    conv_bf16_kernel<<<(nw4 + 255) / 256, 256>>>(wq, wqh, nw4);
    conv_bf16_kernel<<<(nw4 + 255) / 256, 256>>>(wk, wkh, nw4);
    conv_bf16_kernel<<<(nw4 + 255) / 256, 256>>>(wv, wvh, nw4);
    conv_bf16_kernel<<<(nw4 + 255) / 256, 256>>>(wo, woh, nw4);

    dim3 gg(D_MODEL / 128, MTOT / 128);  // (8, 64)
    gemm_bf16<true, false><<<gg, 256, GSM>>>(bxh, wqh, bq, nullptr, qh, MTOT, D_MODEL, D_MODEL);
    gemm_bf16<true, false><<<gg, 256, GSM>>>(bxh, wkh, bk, nullptr, kh, MTOT, D_MODEL, D_MODEL);
    gemm_bf16<true, false><<<gg, 256, GSM>>>(bxh, wvh, bv, nullptr, vh, MTOT, D_MODEL, D_MODEL);

    dim3 ga(SEQ / 128, NHEAD, BATCH);    // (16, 16, 4)
    attn_bf16<<<ga, 256, ASM_TOTAL>>>(qh, kh, vh, ah);

    gemm_bf16<false, true><<<gg, 256, GSM>>>(ah, woh, bo, batch, x, MTOT, D_MODEL, D_MODEL);

    ln_kernel<<<MTOT, 256>>>(x, ln_g, ln_b, (float*)d_out);
}

// round 6
// speedup vs baseline: 9.5870x; 1.3125x over previous
#include <cuda_runtime.h>
#include <cuda_bf16.h>
#include <cstdint>

#define D_MODEL 1024
#define SEQ     2048
#define BATCH   4
#define NHEAD   16
#define DHEAD   64
#define MTOT    (BATCH*SEQ)   // 8192
#define LN_EPS  1e-5f

// ---------------------------------------------------------------------------
// Scratch (no cudaMalloc allowed). bf16 operands, fp32 where accuracy matters.
// ---------------------------------------------------------------------------
__device__ __nv_bfloat16 g_qh[(size_t)MTOT * D_MODEL];
__device__ __nv_bfloat16 g_kh[(size_t)MTOT * D_MODEL];
__device__ __nv_bfloat16 g_vh[(size_t)MTOT * D_MODEL];
__device__ __nv_bfloat16 g_ah[(size_t)MTOT * D_MODEL];   // attention output
__device__ __nv_bfloat16 g_bxh[(size_t)MTOT * D_MODEL];  // bf16 batch
__device__ __nv_bfloat16 g_wqkv[(size_t)3 * D_MODEL * D_MODEL]; // packed q,k,v
__device__ __nv_bfloat16 g_woh[(size_t)D_MODEL * D_MODEL];
__device__ float g_x[(size_t)MTOT * D_MODEL];            // residual sum (fp32)

// ---------------------------------------------------------------------------
// Helpers
// ---------------------------------------------------------------------------
__device__ __forceinline__ uint32_t s2u(const void* p) {
    uint32_t a;
    asm("{ .reg .u64 t; cvta.to.shared.u64 t, %1; cvt.u32.u64 %0, t; }"
        : "=r"(a) : "l"(p));
    return a;
}

#define LDSM4(f0,f1,f2,f3,addr) \
    asm volatile("ldmatrix.sync.aligned.m8n8.x4.shared.b16 {%0,%1,%2,%3}, [%4];" \
                 : "=r"(f0), "=r"(f1), "=r"(f2), "=r"(f3) : "r"(addr))

#define LDSM4T(f0,f1,f2,f3,addr) \
    asm volatile("ldmatrix.sync.aligned.m8n8.x4.trans.shared.b16 {%0,%1,%2,%3}, [%4];" \
                 : "=r"(f0), "=r"(f1), "=r"(f2), "=r"(f3) : "r"(addr))

#define MMA_BF16(d, a, b0, b1) \
    asm volatile("mma.sync.aligned.m16n8k16.row.col.f32.bf16.bf16.f32 " \
                 "{%0,%1,%2,%3}, {%4,%5,%6,%7}, {%8,%9}, {%0,%1,%2,%3};" \
                 : "+f"((d)[0]), "+f"((d)[1]), "+f"((d)[2]), "+f"((d)[3]) \
                 : "r"((a)[0]), "r"((a)[1]), "r"((a)[2]), "r"((a)[3]), \
                   "r"(b0), "r"(b1))

#define CP16(dst, src) \
    asm volatile("cp.async.cg.shared.global [%0], [%1], 16;" \
                 :: "r"(dst), "l"(src) : "memory")

// ---------------------------------------------------------------------------
// fp32 -> bf16 (rn) conversions
// ---------------------------------------------------------------------------
__global__ __launch_bounds__(256)
void conv_bf16_kernel(const float* __restrict__ in, __nv_bfloat16* __restrict__ out, int n4)
{
    int i = blockIdx.x * blockDim.x + threadIdx.x;
    if (i < n4) {
        float4 f = ((const float4*)in)[i];
        ((__nv_bfloat162*)out)[i * 2]     = __floats2bfloat162_rn(f.x, f.y);
        ((__nv_bfloat162*)out)[i * 2 + 1] = __floats2bfloat162_rn(f.z, f.w);
    }
}

// Pack wq, wk, wv -> g_wqkv [3072][1024] bf16
__global__ __launch_bounds__(256)
void conv_wqkv_kernel(const float* __restrict__ wq, const float* __restrict__ wk,
                      const float* __restrict__ wv, __nv_bfloat16* __restrict__ out)
{
    const int per = (D_MODEL * D_MODEL) / 4;   // float4 per weight
    int i = blockIdx.x * blockDim.x + threadIdx.x;
    if (i < 3 * per) {
        int w = i / per, j = i - w * per;
        const float* src = (w == 0) ? wq : (w == 1) ? wk : wv;
        float4 f = ((const float4*)src)[j];
        __nv_bfloat162* dst = (__nv_bfloat162*)(out + (size_t)w * D_MODEL * D_MODEL);
        dst[j * 2]     = __floats2bfloat162_rn(f.x, f.y);
        dst[j * 2 + 1] = __floats2bfloat162_rn(f.z, f.w);
    }
}

// ---------------------------------------------------------------------------
// bf16 mma GEMM. MODE 0: fused QKV (A[M,1024] @ Wqkv[3072,1024]^T, route by
// n-segment to three bf16 outputs, per-segment bias). MODE 1: out-proj
// (fp32 out + residual).
// CTA 128x128, BK=32 halves, NS=4 cp.async stages, 256 threads (8 warps).
// ---------------------------------------------------------------------------
#define GPH   40                    // halves per smem row (32 data + 8 pad)
#define GSTGB (128 * GPH * 2)       // 10240 bytes per operand per stage
#define GSM   (4 * 2 * GSTGB)       // 81920 bytes dynamic smem

template<int MODE>
__global__ __launch_bounds__(256, 2)
void gemm_bf16(const __nv_bfloat16* __restrict__ A, const __nv_bfloat16* __restrict__ W,
               const float* __restrict__ b0p, const float* __restrict__ b1p,
               const float* __restrict__ b2p,
               __nv_bfloat16* __restrict__ o0p, __nv_bfloat16* __restrict__ o1p,
               __nv_bfloat16* __restrict__ o2p,
               const float* __restrict__ resid, float* __restrict__ Cf,
               int M, int K)
{
    extern __shared__ __align__(16) char gsm[];
    const uint32_t sA = s2u(gsm);
    const uint32_t sB = sA + 4 * GSTGB;

    const int tid  = threadIdx.x;
    const int wid  = tid >> 5;
    const int lane = tid & 31;
    const int wm   = wid & 1;
    const int wn   = wid >> 1;
    const int m0   = blockIdx.y * 128;
    const int n0   = blockIdx.x * 128;     // global n (may span 3072 in MODE 0)
    const int NCH  = K / 32;               // 32

    // Output routing
    const float* bias;
    __nv_bfloat16* Cb = nullptr;
    int nloc0;
    if (MODE == 0) {
        int seg = n0 >> 10;
        bias  = (seg == 0) ? b0p : (seg == 1) ? b1p : b2p;
        Cb    = (seg == 0) ? o0p : (seg == 1) ? o1p : o2p;
        nloc0 = n0 & 1023;
    } else {
        bias  = b0p;
        nloc0 = n0;
    }

    const int r_ld = tid >> 2;       // 0..63 base row
    const int g_ld = tid & 3;        // 16B granule (8 halves)
    const __nv_bfloat16* Abase = A + (size_t)m0 * K + g_ld * 8;
    const __nv_bfloat16* Wbase = W + (size_t)n0 * K + g_ld * 8;

    auto issue = [&](int c) {
        if (c < NCH) {
            int st = c & 3;
            uint32_t da = sA + st * GSTGB;
            uint32_t db = sB + st * GSTGB;
            long ko = (long)c * 32;
#pragma unroll
            for (int q = 0; q < 2; q++) {
                int row = r_ld + q * 64;
                CP16(da + row * (GPH * 2) + g_ld * 16, Abase + (size_t)row * K + ko);
                CP16(db + row * (GPH * 2) + g_ld * 16, Wbase + (size_t)row * K + ko);
            }
        }
        asm volatile("cp.async.commit_group;" ::: "memory");
    };

    float acc[4][4][4];
#pragma unroll
    for (int i = 0; i < 4; i++)
#pragma unroll
        for (int j = 0; j < 4; j++)
#pragma unroll
            for (int k = 0; k < 4; k++) acc[i][j][k] = 0.0f;

    const int laneA_r = ((lane >> 3) & 1) * 8 + (lane & 7);
    const int laneA_g = lane >> 4;
    const int laneB_r = (lane >> 4) * 8 + (lane & 7);
    const int laneB_g = (lane >> 3) & 1;

    issue(0); issue(1); issue(2);

    for (int c = 0; c < NCH; c++) {
        asm volatile("cp.async.wait_group 2;" ::: "memory");
        __syncthreads();
        issue(c + 3);

        int st = c & 3;
        uint32_t aSt = sA + st * GSTGB;
        uint32_t bSt = sB + st * GSTGB;

#pragma unroll
        for (int j = 0; j < 2; j++) {          // two k16 steps per BK=32
            uint32_t aF[4][4], bF[2][4];
#pragma unroll
            for (int mt = 0; mt < 4; mt++) {
                uint32_t addr = aSt + (wm * 64 + mt * 16 + laneA_r) * (GPH * 2)
                                    + (laneA_g + 2 * j) * 16;
                LDSM4(aF[mt][0], aF[mt][1], aF[mt][2], aF[mt][3], addr);
            }
#pragma unroll
            for (int np = 0; np < 2; np++) {
                uint32_t addr = bSt + (wn * 32 + np * 16 + laneB_r) * (GPH * 2)
                                    + (laneB_g + 2 * j) * 16;
                LDSM4(bF[np][0], bF[np][1], bF[np][2], bF[np][3], addr);
            }
#pragma unroll
            for (int mt = 0; mt < 4; mt++) {
#pragma unroll
                for (int t = 0; t < 4; t++) {
                    MMA_BF16(acc[mt][t], aF[mt],
                             bF[t >> 1][(t & 1) * 2], bF[t >> 1][(t & 1) * 2 + 1]);
                }
            }
        }
    }

    // Epilogue (output row stride is always 1024)
    const int rb = lane >> 2;
    const int cb = (lane & 3) * 2;
#pragma unroll
    for (int mt = 0; mt < 4; mt++) {
#pragma unroll
        for (int t = 0; t < 4; t++) {
            int nl = nloc0 + wn * 32 + t * 8 + cb;
            float2 bv = *(const float2*)(bias + nl);
            int row0 = m0 + wm * 64 + mt * 16 + rb;
            int row1 = row0 + 8;
            float v00 = acc[mt][t][0] + bv.x;
            float v01 = acc[mt][t][1] + bv.y;
            float v10 = acc[mt][t][2] + bv.x;
            float v11 = acc[mt][t][3] + bv.y;
            if (MODE == 0) {
                *(__nv_bfloat162*)(Cb + (size_t)row0 * D_MODEL + nl) = __floats2bfloat162_rn(v00, v01);
                *(__nv_bfloat162*)(Cb + (size_t)row1 * D_MODEL + nl) = __floats2bfloat162_rn(v10, v11);
            } else {
                float2 r0 = *(const float2*)(resid + (size_t)row0 * D_MODEL + nl);
                float2 r1 = *(const float2*)(resid + (size_t)row1 * D_MODEL + nl);
                *(float2*)(Cf + (size_t)row0 * D_MODEL + nl) = make_float2(v00 + r0.x, v01 + r0.y);
                *(float2*)(Cf + (size_t)row1 * D_MODEL + nl) = make_float2(v10 + r1.x, v11 + r1.y);
            }
        }
    }
}

// ---------------------------------------------------------------------------
// bf16 tensor-core flash attention (fp32 accum + softmax).
// grid = (SEQ/128, NHEAD, BATCH) = (16,16,4); 256 threads = 8 warps.
// Warp w owns query rows 16w..16w+15. K tiles of 64 keys.
// Double-buffered cp.async K/V loads; V kept [key][d], read with
// ldmatrix.trans in the PV phase (no smem transpose).
// Smem: sK[2][64][72] | sV[2][64][72] | sQ[128][72] | sP[128][72] = 72 KB.
// ---------------------------------------------------------------------------
#define APH    72
#define APB    (APH * 2)            // 144 bytes row pitch
#define KSTG   (64 * APB)           // 9216 per stage
#define AOFF_K  0
#define AOFF_V  (2 * KSTG)          // 18432
#define AOFF_Q  (4 * KSTG)          // 36864
#define AOFF_P  (AOFF_Q + 128 * APB) // 55296
#define ASM_TOTAL (AOFF_P + 128 * APB) // 73728

__global__ __launch_bounds__(256, 2)
void attn_bf16(const __nv_bfloat16* __restrict__ Q,
               const __nv_bfloat16* __restrict__ Kg,
               const __nv_bfloat16* __restrict__ Vg,
               __nv_bfloat16* __restrict__ Og)
{
    extern __shared__ __align__(16) char asmem[];
    const uint32_t sb = s2u(asmem);
    const uint32_t sK = sb + AOFF_K;
    const uint32_t sV = sb + AOFF_V;
    const uint32_t sQ = sb + AOFF_Q;
    const uint32_t sP = sb + AOFF_P;
    __nv_bfloat16* smQ = (__nv_bfloat16*)(asmem + AOFF_Q);
    __nv_bfloat16* smP = (__nv_bfloat16*)(asmem + AOFF_P);

    const int qt   = blockIdx.x;
    const int h    = blockIdx.y;
    const int b    = blockIdx.z;
    const int tid  = threadIdx.x;
    const int warp = tid >> 5;
    const int lane = tid & 31;

    const size_t base = ((size_t)b * SEQ) * D_MODEL + (size_t)h * DHEAD;
    const int NT = SEQ / 64;  // 32

    auto issue_kv = [&](int kt) {
        if (kt < NT) {
            int st = kt & 1;
            uint32_t kd = sK + st * KSTG;
            uint32_t vd = sV + st * KSTG;
            const __nv_bfloat16* kp = Kg + base + (size_t)(kt * 64) * D_MODEL;
            const __nv_bfloat16* vp = Vg + base + (size_t)(kt * 64) * D_MODEL;
#pragma unroll
            for (int q = 0; q < 2; q++) {
                int id = tid + q * 256;
                int r = id >> 3, g = id & 7;
                CP16(kd + r * APB + g * 16, kp + (size_t)r * D_MODEL + g * 8);
                CP16(vd + r * APB + g * 16, vp + (size_t)r * D_MODEL + g * 8);
            }
        }
        asm volatile("cp.async.commit_group;" ::: "memory");
    };

    // Load Q tile (128 x 64 halves)
    for (int i = tid; i < 1024; i += 256) {
        int r = i >> 3;
        int g = i & 7;
        uint4 f = *(const uint4*)(Q + base + (size_t)(qt * 128 + r) * D_MODEL + g * 8);
        *(uint4*)(smQ + r * APH + g * 8) = f;
    }

    const int laneA_r = ((lane >> 3) & 1) * 8 + (lane & 7);
    const int laneA_g = lane >> 4;
    const int laneB_r = (lane >> 4) * 8 + (lane & 7);
    const int laneB_g = (lane >> 3) & 1;
    const int laneV_key  = ((lane >> 3) & 1) * 8 + (lane & 7);
    const int laneV_doff = (lane >> 4) * 8;

    float m0 = -1e30f, m1 = -1e30f, l0 = 0.0f, l1 = 0.0f;
    float o[8][4];
#pragma unroll
    for (int nt = 0; nt < 8; nt++)
#pragma unroll
        for (int i = 0; i < 4; i++) o[nt][i] = 0.0f;

    issue_kv(0);

    for (int kt = 0; kt < NT; kt++) {
        issue_kv(kt + 1);
        asm volatile("cp.async.wait_group 1;" ::: "memory");
        __syncthreads();

        int st = kt & 1;
        uint32_t kSt = sK + st * KSTG;
        uint32_t vSt = sV + st * KSTG;

        // S = Q @ K^T  (4 k16 steps over d=64; 8 n8-tiles over 64 keys)
        float s[8][4];
#pragma unroll
        for (int nt = 0; nt < 8; nt++)
#pragma unroll
            for (int i = 0; i < 4; i++) s[nt][i] = 0.0f;

#pragma unroll
        for (int j = 0; j < 4; j++) {
            uint32_t aF[4];
            LDSM4(aF[0], aF[1], aF[2], aF[3],
                  sQ + (warp * 16 + laneA_r) * APB + (laneA_g + 2 * j) * 16);
            uint32_t bF[4][4];
#pragma unroll
            for (int np = 0; np < 4; np++) {
                LDSM4(bF[np][0], bF[np][1], bF[np][2], bF[np][3],
                      kSt + (np * 16 + laneB_r) * APB + (laneB_g + 2 * j) * 16);
            }
#pragma unroll
            for (int nt = 0; nt < 8; nt++)
                MMA_BF16(s[nt], aF, bF[nt >> 1][(nt & 1) * 2], bF[nt >> 1][(nt & 1) * 2 + 1]);
        }

        // scale + online softmax (rows r0 and r0+8 of warp's m16)
        float mx0 = -1e30f, mx1 = -1e30f;
#pragma unroll
        for (int nt = 0; nt < 8; nt++) {
            s[nt][0] *= 0.125f; s[nt][1] *= 0.125f;
            s[nt][2] *= 0.125f; s[nt][3] *= 0.125f;
            mx0 = fmaxf(mx0, fmaxf(s[nt][0], s[nt][1]));
            mx1 = fmaxf(mx1, fmaxf(s[nt][2], s[nt][3]));
        }
        mx0 = fmaxf(mx0, __shfl_xor_sync(0xffffffffu, mx0, 1));
        mx0 = fmaxf(mx0, __shfl_xor_sync(0xffffffffu, mx0, 2));
        mx1 = fmaxf(mx1, __shfl_xor_sync(0xffffffffu, mx1, 1));
        mx1 = fmaxf(mx1, __shfl_xor_sync(0xffffffffu, mx1, 2));
        float nm0 = fmaxf(m0, mx0), nm1 = fmaxf(m1, mx1);
        float a0 = __expf(m0 - nm0), a1 = __expf(m1 - nm1);

        float sum0 = 0.0f, sum1 = 0.0f;
        int pr0 = warp * 16 + (lane >> 2);
        int pc0 = (lane & 3) * 2;
#pragma unroll
        for (int nt = 0; nt < 8; nt++) {
            float e00 = __expf(s[nt][0] - nm0);
            float e01 = __expf(s[nt][1] - nm0);
            float e10 = __expf(s[nt][2] - nm1);
            float e11 = __expf(s[nt][3] - nm1);
            sum0 += e00 + e01;
            sum1 += e10 + e11;
            *(__nv_bfloat162*)(smP + pr0 * APH + nt * 8 + pc0)       = __floats2bfloat162_rn(e00, e01);
            *(__nv_bfloat162*)(smP + (pr0 + 8) * APH + nt * 8 + pc0) = __floats2bfloat162_rn(e10, e11);
        }
        sum0 += __shfl_xor_sync(0xffffffffu, sum0, 1);
        sum0 += __shfl_xor_sync(0xffffffffu, sum0, 2);
        sum1 += __shfl_xor_sync(0xffffffffu, sum1, 1);
        sum1 += __shfl_xor_sync(0xffffffffu, sum1, 2);
        l0 = l0 * a0 + sum0;
        l1 = l1 * a1 + sum1;
        m0 = nm0; m1 = nm1;
#pragma unroll
        for (int nt = 0; nt < 8; nt++) {
            o[nt][0] *= a0; o[nt][1] *= a0;
            o[nt][2] *= a1; o[nt][3] *= a1;
        }
        __syncwarp();

        // O += P @ V : V is [key][d]; ldmatrix.trans yields V^T fragments.
#pragma unroll
        for (int j = 0; j < 4; j++) {
            uint32_t aF[4];
            LDSM4(aF[0], aF[1], aF[2], aF[3],
                  sP + (warp * 16 + laneA_r) * APB + (laneA_g + 2 * j) * 16);
            uint32_t tF[4][4];
#pragma unroll
            for (int pr = 0; pr < 4; pr++) {   // d16 pair
                uint32_t addr = vSt + (j * 16 + laneV_key) * APB
                                    + (pr * 16 + laneV_doff) * 2;
                LDSM4T(tF[pr][0], tF[pr][1], tF[pr][2], tF[pr][3], addr);
            }
#pragma unroll
            for (int nt = 0; nt < 8; nt++)
                MMA_BF16(o[nt], aF, tF[nt >> 1][(nt & 1) * 2], tF[nt >> 1][(nt & 1) * 2 + 1]);
        }
        __syncthreads();   // all warps done with stage st before it is refilled
    }

    // Epilogue: normalize, convert bf16
    float inv0 = 1.0f / l0, inv1 = 1.0f / l1;
    int r0 = qt * 128 + warp * 16 + (lane >> 2);
    int c0 = (lane & 3) * 2;
#pragma unroll
    for (int nt = 0; nt < 8; nt++) {
        size_t p0 = base + (size_t)r0 * D_MODEL + nt * 8 + c0;
        size_t p1 = base + (size_t)(r0 + 8) * D_MODEL + nt * 8 + c0;
        *(__nv_bfloat162*)(Og + p0) = __floats2bfloat162_rn(o[nt][0] * inv0, o[nt][1] * inv0);
        *(__nv_bfloat162*)(Og + p1) = __floats2bfloat162_rn(o[nt][2] * inv1, o[nt][3] * inv1);
    }
}

// ---------------------------------------------------------------------------
// LayerNorm
// ---------------------------------------------------------------------------
__global__ __launch_bounds__(256)
void ln_kernel(const float* __restrict__ X,
               const float* __restrict__ gamma,
               const float* __restrict__ beta,
               float* __restrict__ out)
{
    const int row = blockIdx.x;
    const int tid = threadIdx.x;
    const float* x = X + (size_t)row * D_MODEL;

    float4 f = *(const float4*)(x + tid * 4);
    float s  = f.x + f.y + f.z + f.w;
    float ss = f.x * f.x + f.y * f.y + f.z * f.z + f.w * f.w;

#pragma unroll
    for (int o = 16; o > 0; o >>= 1) {
        s  += __shfl_xor_sync(0xffffffffu, s,  o);
        ss += __shfl_xor_sync(0xffffffffu, ss, o);
    }

    __shared__ float sh[16];
    const int warp = tid >> 5, lane = tid & 31;
    if (lane == 0) { sh[warp] = s; sh[warp + 8] = ss; }
    __syncthreads();
    if (tid == 0) {
        float S = 0.0f, SS = 0.0f;
#pragma unroll
        for (int w = 0; w < 8; w++) { S += sh[w]; SS += sh[w + 8]; }
        float mu  = S * (1.0f / D_MODEL);
        float var = SS * (1.0f / D_MODEL) - mu * mu;
        sh[0] = mu;
        sh[1] = rsqrtf(var + LN_EPS);
    }
    __syncthreads();
    float mu = sh[0], rstd = sh[1];

    float4 gm = *(const float4*)(gamma + tid * 4);
    float4 bt = *(const float4*)(beta  + tid * 4);
    float4 o4;
    o4.x = (f.x - mu) * rstd * gm.x + bt.x;
    o4.y = (f.y - mu) * rstd * gm.y + bt.y;
    o4.z = (f.z - mu) * rstd * gm.z + bt.z;
    o4.w = (f.w - mu) * rstd * gm.w + bt.w;
    *(float4*)(out + (size_t)row * D_MODEL + tid * 4) = o4;
}

// ---------------------------------------------------------------------------
// Launch
// ---------------------------------------------------------------------------
extern "C" void kernel_launch(void* const* d_in, const int* in_sizes, int n_in,
                              void* d_out, int out_size)
{
    const float* batch = (const float*)d_in[0];
    const float* wq    = (const float*)d_in[1];
    const float* bq    = (const float*)d_in[2];
    const float* wk    = (const float*)d_in[3];
    const float* bk    = (const float*)d_in[4];
    const float* wv    = (const float*)d_in[5];
    const float* bv    = (const float*)d_in[6];
    const float* wo    = (const float*)d_in[7];
    const float* bo    = (const float*)d_in[8];
    const float* ln_g  = (const float*)d_in[9];
    const float* ln_b  = (const float*)d_in[10];

    __nv_bfloat16 *qh, *kh, *vh, *ah, *bxh, *wqkvh, *woh;
    float *x;
    cudaGetSymbolAddress((void**)&qh,    g_qh);
    cudaGetSymbolAddress((void**)&kh,    g_kh);
    cudaGetSymbolAddress((void**)&vh,    g_vh);
    cudaGetSymbolAddress((void**)&ah,    g_ah);
    cudaGetSymbolAddress((void**)&bxh,   g_bxh);
    cudaGetSymbolAddress((void**)&wqkvh, g_wqkv);
    cudaGetSymbolAddress((void**)&woh,   g_woh);
    cudaGetSymbolAddress((void**)&x,     g_x);

    static bool attr_done = false;
    if (!attr_done) {
        cudaFuncSetAttribute(gemm_bf16<0>, cudaFuncAttributeMaxDynamicSharedMemorySize, GSM);
        cudaFuncSetAttribute(gemm_bf16<1>, cudaFuncAttributeMaxDynamicSharedMemorySize, GSM);
        cudaFuncSetAttribute(attn_bf16, cudaFuncAttributeMaxDynamicSharedMemorySize, ASM_TOTAL);
        attr_done = true;
    }

    // fp32 -> bf16 conversions (3 launches)
    const int nb4 = MTOT * D_MODEL / 4;
    const int nw4 = D_MODEL * D_MODEL / 4;
    conv_bf16_kernel<<<(nb4 + 255) / 256, 256>>>(batch, bxh, nb4);
    conv_wqkv_kernel<<<(3 * nw4 + 255) / 256, 256>>>(wq, wk, wv, wqkvh);
    conv_bf16_kernel<<<(nw4 + 255) / 256, 256>>>(wo, woh, nw4);

    // Fused QKV projection: [8192,1024] @ [3072,1024]^T
    dim3 gq(3 * D_MODEL / 128, MTOT / 128);  // (24, 64)
    gemm_bf16<0><<<gq, 256, GSM>>>(bxh, wqkvh, bq, bk, bv, qh, kh, vh,
                                   nullptr, nullptr, MTOT, D_MODEL);

    dim3 ga(SEQ / 128, NHEAD, BATCH);        // (16, 16, 4)
    attn_bf16<<<ga, 256, ASM_TOTAL>>>(qh, kh, vh, ah);

    // Out-projection + residual (fp32 out)
    dim3 gg(D_MODEL / 128, MTOT / 128);      // (8, 64)
    gemm_bf16<1><<<gg, 256, GSM>>>(ah, woh, bo, nullptr, nullptr,
                                   nullptr, nullptr, nullptr, batch, x,
                                   MTOT, D_MODEL);

    ln_kernel<<<MTOT, 256>>>(x, ln_g, ln_b, (float*)d_out);
}

// round 7
// speedup vs baseline: 9.9335x; 1.0361x over previous
#include <cuda_runtime.h>
#include <cuda_bf16.h>
#include <cstdint>

#define D_MODEL 1024
#define SEQ     2048
#define BATCH   4
#define NHEAD   16
#define DHEAD   64
#define MTOT    (BATCH*SEQ)   // 8192
#define LN_EPS  1e-5f

// ---------------------------------------------------------------------------
// Scratch (no cudaMalloc allowed). bf16 operands, fp32 where accuracy matters.
// ---------------------------------------------------------------------------
__device__ __nv_bfloat16 g_qh[(size_t)MTOT * D_MODEL];
__device__ __nv_bfloat16 g_kh[(size_t)MTOT * D_MODEL];
__device__ __nv_bfloat16 g_vh[(size_t)MTOT * D_MODEL];
__device__ __nv_bfloat16 g_ah[(size_t)MTOT * D_MODEL];   // attention output
__device__ __nv_bfloat16 g_bxh[(size_t)MTOT * D_MODEL];  // bf16 batch
__device__ __nv_bfloat16 g_wqkv[(size_t)3 * D_MODEL * D_MODEL]; // packed q,k,v
__device__ __nv_bfloat16 g_woh[(size_t)D_MODEL * D_MODEL];
__device__ float g_x[(size_t)MTOT * D_MODEL];            // residual sum (fp32)

// ---------------------------------------------------------------------------
// Helpers
// ---------------------------------------------------------------------------
__device__ __forceinline__ uint32_t s2u(const void* p) {
    uint32_t a;
    asm("{ .reg .u64 t; cvta.to.shared.u64 t, %1; cvt.u32.u64 %0, t; }"
        : "=r"(a) : "l"(p));
    return a;
}

#define LDSM4(f0,f1,f2,f3,addr) \
    asm volatile("ldmatrix.sync.aligned.m8n8.x4.shared.b16 {%0,%1,%2,%3}, [%4];" \
                 : "=r"(f0), "=r"(f1), "=r"(f2), "=r"(f3) : "r"(addr))

#define LDSM4T(f0,f1,f2,f3,addr) \
    asm volatile("ldmatrix.sync.aligned.m8n8.x4.trans.shared.b16 {%0,%1,%2,%3}, [%4];" \
                 : "=r"(f0), "=r"(f1), "=r"(f2), "=r"(f3) : "r"(addr))

#define MMA_BF16(d, a, b0, b1) \
    asm volatile("mma.sync.aligned.m16n8k16.row.col.f32.bf16.bf16.f32 " \
                 "{%0,%1,%2,%3}, {%4,%5,%6,%7}, {%8,%9}, {%0,%1,%2,%3};" \
                 : "+f"((d)[0]), "+f"((d)[1]), "+f"((d)[2]), "+f"((d)[3]) \
                 : "r"((a)[0]), "r"((a)[1]), "r"((a)[2]), "r"((a)[3]), \
                   "r"(b0), "r"(b1))

#define CP16(dst, src) \
    asm volatile("cp.async.cg.shared.global [%0], [%1], 16;" \
                 :: "r"(dst), "l"(src) : "memory")

// ---------------------------------------------------------------------------
// fp32 -> bf16 (rn) conversions
// ---------------------------------------------------------------------------
__global__ __launch_bounds__(256)
void conv_bf16_kernel(const float* __restrict__ in, __nv_bfloat16* __restrict__ out, int n4)
{
    int i = blockIdx.x * blockDim.x + threadIdx.x;
    if (i < n4) {
        float4 f = ((const float4*)in)[i];
        ((__nv_bfloat162*)out)[i * 2]     = __floats2bfloat162_rn(f.x, f.y);
        ((__nv_bfloat162*)out)[i * 2 + 1] = __floats2bfloat162_rn(f.z, f.w);
    }
}

// Pack wq, wk, wv -> g_wqkv [3072][1024] bf16
__global__ __launch_bounds__(256)
void conv_wqkv_kernel(const float* __restrict__ wq, const float* __restrict__ wk,
                      const float* __restrict__ wv, __nv_bfloat16* __restrict__ out)
{
    const int per = (D_MODEL * D_MODEL) / 4;
    int i = blockIdx.x * blockDim.x + threadIdx.x;
    if (i < 3 * per) {
        int w = i / per, j = i - w * per;
        const float* src = (w == 0) ? wq : (w == 1) ? wk : wv;
        float4 f = ((const float4*)src)[j];
        __nv_bfloat162* dst = (__nv_bfloat162*)(out + (size_t)w * D_MODEL * D_MODEL);
        dst[j * 2]     = __floats2bfloat162_rn(f.x, f.y);
        dst[j * 2 + 1] = __floats2bfloat162_rn(f.z, f.w);
    }
}

// ---------------------------------------------------------------------------
// bf16 mma GEMM. MODE 0: fused QKV (A[M,1024] @ Wqkv[3072,1024]^T, route by
// n-segment). MODE 1: out-proj (fp32 out + residual).
// CTA 128x128, BK=64 halves, NS=3 cp.async stages, 256 threads (8 warps).
// One __syncthreads per 64-deep chunk (16 chunks total).
// Smem row pitch 72 halves (144B): 8-row ldmatrix phases conflict-free.
// ---------------------------------------------------------------------------
#define GPH   72                    // halves per smem row (64 data + 8 pad)
#define GSTGB (128 * GPH * 2)       // 18432 bytes per operand per stage
#define GSM   (3 * 2 * GSTGB)       // 110592 bytes dynamic smem

template<int MODE>
__global__ __launch_bounds__(256, 2)
void gemm_bf16(const __nv_bfloat16* __restrict__ A, const __nv_bfloat16* __restrict__ W,
               const float* __restrict__ b0p, const float* __restrict__ b1p,
               const float* __restrict__ b2p,
               __nv_bfloat16* __restrict__ o0p, __nv_bfloat16* __restrict__ o1p,
               __nv_bfloat16* __restrict__ o2p,
               const float* __restrict__ resid, float* __restrict__ Cf,
               int M, int K)
{
    extern __shared__ __align__(16) char gsm[];
    const uint32_t sA = s2u(gsm);
    const uint32_t sB = sA + 3 * GSTGB;

    const int tid  = threadIdx.x;
    const int wid  = tid >> 5;
    const int lane = tid & 31;
    const int wm   = wid & 1;
    const int wn   = wid >> 1;
    const int m0   = blockIdx.y * 128;
    const int n0   = blockIdx.x * 128;
    const int NCH  = K / 64;               // 16

    // Output routing
    const float* bias;
    __nv_bfloat16* Cb = nullptr;
    int nloc0;
    if (MODE == 0) {
        int seg = n0 >> 10;
        bias  = (seg == 0) ? b0p : (seg == 1) ? b1p : b2p;
        Cb    = (seg == 0) ? o0p : (seg == 1) ? o1p : o2p;
        nloc0 = n0 & 1023;
    } else {
        bias  = b0p;
        nloc0 = n0;
    }

    const int r_ld = tid >> 3;       // 0..31 base row
    const int g_ld = tid & 7;        // 16B granule (8 halves) within 64-half chunk
    const __nv_bfloat16* Abase = A + (size_t)m0 * K + g_ld * 8;
    const __nv_bfloat16* Wbase = W + (size_t)n0 * K + g_ld * 8;

    auto issue = [&](int c) {
        if (c < NCH) {
            int st = c - (c / 3) * 3;
            uint32_t da = sA + st * GSTGB;
            uint32_t db = sB + st * GSTGB;
            long ko = (long)c * 64;
#pragma unroll
            for (int q = 0; q < 4; q++) {
                int row = r_ld + q * 32;
                CP16(da + row * (GPH * 2) + g_ld * 16, Abase + (size_t)row * K + ko);
                CP16(db + row * (GPH * 2) + g_ld * 16, Wbase + (size_t)row * K + ko);
            }
        }
        asm volatile("cp.async.commit_group;" ::: "memory");
    };

    float acc[4][4][4];
#pragma unroll
    for (int i = 0; i < 4; i++)
#pragma unroll
        for (int j = 0; j < 4; j++)
#pragma unroll
            for (int k = 0; k < 4; k++) acc[i][j][k] = 0.0f;

    const int laneA_r = ((lane >> 3) & 1) * 8 + (lane & 7);
    const int laneA_g = lane >> 4;
    const int laneB_r = (lane >> 4) * 8 + (lane & 7);
    const int laneB_g = (lane >> 3) & 1;

    issue(0); issue(1);

    for (int c = 0; c < NCH; c++) {
        asm volatile("cp.async.wait_group 1;" ::: "memory");
        __syncthreads();
        issue(c + 2);

        int st = c - (c / 3) * 3;
        uint32_t aSt = sA + st * GSTGB;
        uint32_t bSt = sB + st * GSTGB;

#pragma unroll
        for (int j = 0; j < 4; j++) {          // four k16 steps per BK=64
            uint32_t aF[4][4], bF[2][4];
#pragma unroll
            for (int mt = 0; mt < 4; mt++) {
                uint32_t addr = aSt + (wm * 64 + mt * 16 + laneA_r) * (GPH * 2)
                                    + (laneA_g + 2 * j) * 16;
                LDSM4(aF[mt][0], aF[mt][1], aF[mt][2], aF[mt][3], addr);
            }
#pragma unroll
            for (int np = 0; np < 2; np++) {
                uint32_t addr = bSt + (wn * 32 + np * 16 + laneB_r) * (GPH * 2)
                                    + (laneB_g + 2 * j) * 16;
                LDSM4(bF[np][0], bF[np][1], bF[np][2], bF[np][3], addr);
            }
#pragma unroll
            for (int mt = 0; mt < 4; mt++) {
#pragma unroll
                for (int t = 0; t < 4; t++) {
                    MMA_BF16(acc[mt][t], aF[mt],
                             bF[t >> 1][(t & 1) * 2], bF[t >> 1][(t & 1) * 2 + 1]);
                }
            }
        }
    }

    // Epilogue (output row stride is always 1024)
    const int rb = lane >> 2;
    const int cb = (lane & 3) * 2;
#pragma unroll
    for (int mt = 0; mt < 4; mt++) {
#pragma unroll
        for (int t = 0; t < 4; t++) {
            int nl = nloc0 + wn * 32 + t * 8 + cb;
            float2 bv = *(const float2*)(bias + nl);
            int row0 = m0 + wm * 64 + mt * 16 + rb;
            int row1 = row0 + 8;
            float v00 = acc[mt][t][0] + bv.x;
            float v01 = acc[mt][t][1] + bv.y;
            float v10 = acc[mt][t][2] + bv.x;
            float v11 = acc[mt][t][3] + bv.y;
            if (MODE == 0) {
                *(__nv_bfloat162*)(Cb + (size_t)row0 * D_MODEL + nl) = __floats2bfloat162_rn(v00, v01);
                *(__nv_bfloat162*)(Cb + (size_t)row1 * D_MODEL + nl) = __floats2bfloat162_rn(v10, v11);
            } else {
                float2 r0 = *(const float2*)(resid + (size_t)row0 * D_MODEL + nl);
                float2 r1 = *(const float2*)(resid + (size_t)row1 * D_MODEL + nl);
                *(float2*)(Cf + (size_t)row0 * D_MODEL + nl) = make_float2(v00 + r0.x, v01 + r0.y);
                *(float2*)(Cf + (size_t)row1 * D_MODEL + nl) = make_float2(v10 + r1.x, v11 + r1.y);
            }
        }
    }
}

// ---------------------------------------------------------------------------
// bf16 tensor-core flash attention (fp32 accum + softmax).
// grid = (SEQ/128, NHEAD, BATCH) = (16,16,4); 256 threads = 8 warps.
// Warp w owns query rows 16w..16w+15. K tiles of 64 keys.
// 3-stage cp.async K/V ring -> ONE __syncthreads per key tile.
// V kept [key][d], read with ldmatrix.trans in the PV phase.
// Smem: sK[3][64][72] | sV[3][64][72] | sQ[128][72] | sP[128][72] = 90 KB.
// ---------------------------------------------------------------------------
#define APH    72
#define APB    (APH * 2)            // 144 bytes row pitch
#define KSTG   (64 * APB)           // 9216 per stage
#define AOFF_K  0
#define AOFF_V  (3 * KSTG)           // 27648
#define AOFF_Q  (6 * KSTG)           // 55296
#define AOFF_P  (AOFF_Q + 128 * APB) // 73728
#define ASM_TOTAL (AOFF_P + 128 * APB) // 92160

__global__ __launch_bounds__(256, 2)
void attn_bf16(const __nv_bfloat16* __restrict__ Q,
               const __nv_bfloat16* __restrict__ Kg,
               const __nv_bfloat16* __restrict__ Vg,
               __nv_bfloat16* __restrict__ Og)
{
    extern __shared__ __align__(16) char asmem[];
    const uint32_t sb = s2u(asmem);
    const uint32_t sK = sb + AOFF_K;
    const uint32_t sV = sb + AOFF_V;
    const uint32_t sQ = sb + AOFF_Q;
    const uint32_t sP = sb + AOFF_P;
    __nv_bfloat16* smQ = (__nv_bfloat16*)(asmem + AOFF_Q);
    __nv_bfloat16* smP = (__nv_bfloat16*)(asmem + AOFF_P);

    const int qt   = blockIdx.x;
    const int h    = blockIdx.y;
    const int b    = blockIdx.z;
    const int tid  = threadIdx.x;
    const int warp = tid >> 5;
    const int lane = tid & 31;

    const size_t base = ((size_t)b * SEQ) * D_MODEL + (size_t)h * DHEAD;
    const int NT = SEQ / 64;  // 32

    auto issue_kv = [&](int kt) {
        if (kt < NT) {
            int st = kt - (kt / 3) * 3;
            uint32_t kd = sK + st * KSTG;
            uint32_t vd = sV + st * KSTG;
            const __nv_bfloat16* kp = Kg + base + (size_t)(kt * 64) * D_MODEL;
            const __nv_bfloat16* vp = Vg + base + (size_t)(kt * 64) * D_MODEL;
#pragma unroll
            for (int q = 0; q < 2; q++) {
                int id = tid + q * 256;
                int r = id >> 3, g = id & 7;
                CP16(kd + r * APB + g * 16, kp + (size_t)r * D_MODEL + g * 8);
                CP16(vd + r * APB + g * 16, vp + (size_t)r * D_MODEL + g * 8);
            }
        }
        asm volatile("cp.async.commit_group;" ::: "memory");
    };

    // Load Q tile (128 x 64 halves)
    for (int i = tid; i < 1024; i += 256) {
        int r = i >> 3;
        int g = i & 7;
        uint4 f = *(const uint4*)(Q + base + (size_t)(qt * 128 + r) * D_MODEL + g * 8);
        *(uint4*)(smQ + r * APH + g * 8) = f;
    }

    const int laneA_r = ((lane >> 3) & 1) * 8 + (lane & 7);
    const int laneA_g = lane >> 4;
    const int laneB_r = (lane >> 4) * 8 + (lane & 7);
    const int laneB_g = (lane >> 3) & 1;
    const int laneV_key  = ((lane >> 3) & 1) * 8 + (lane & 7);
    const int laneV_doff = (lane >> 4) * 8;

    float m0 = -1e30f, m1 = -1e30f, l0 = 0.0f, l1 = 0.0f;
    float o[8][4];
#pragma unroll
    for (int nt = 0; nt < 8; nt++)
#pragma unroll
        for (int i = 0; i < 4; i++) o[nt][i] = 0.0f;

    issue_kv(0);
    issue_kv(1);

    for (int kt = 0; kt < NT; kt++) {
        asm volatile("cp.async.wait_group 1;" ::: "memory");
        __syncthreads();       // all warps done with stage (kt-1)%3 (== (kt+2)%3)
        issue_kv(kt + 2);

        int st = kt - (kt / 3) * 3;
        uint32_t kSt = sK + st * KSTG;
        uint32_t vSt = sV + st * KSTG;

        // S = Q @ K^T  (4 k16 steps over d=64; 8 n8-tiles over 64 keys)
        float s[8][4];
#pragma unroll
        for (int nt = 0; nt < 8; nt++)
#pragma unroll
            for (int i = 0; i < 4; i++) s[nt][i] = 0.0f;

#pragma unroll
        for (int j = 0; j < 4; j++) {
            uint32_t aF[4];
            LDSM4(aF[0], aF[1], aF[2], aF[3],
                  sQ + (warp * 16 + laneA_r) * APB + (laneA_g + 2 * j) * 16);
            uint32_t bF[4][4];
#pragma unroll
            for (int np = 0; np < 4; np++) {
                LDSM4(bF[np][0], bF[np][1], bF[np][2], bF[np][3],
                      kSt + (np * 16 + laneB_r) * APB + (laneB_g + 2 * j) * 16);
            }
#pragma unroll
            for (int nt = 0; nt < 8; nt++)
                MMA_BF16(s[nt], aF, bF[nt >> 1][(nt & 1) * 2], bF[nt >> 1][(nt & 1) * 2 + 1]);
        }

        // scale + online softmax (rows r0 and r0+8 of warp's m16)
        float mx0 = -1e30f, mx1 = -1e30f;
#pragma unroll
        for (int nt = 0; nt < 8; nt++) {
            s[nt][0] *= 0.125f; s[nt][1] *= 0.125f;
            s[nt][2] *= 0.125f; s[nt][3] *= 0.125f;
            mx0 = fmaxf(mx0, fmaxf(s[nt][0], s[nt][1]));
            mx1 = fmaxf(mx1, fmaxf(s[nt][2], s[nt][3]));
        }
        mx0 = fmaxf(mx0, __shfl_xor_sync(0xffffffffu, mx0, 1));
        mx0 = fmaxf(mx0, __shfl_xor_sync(0xffffffffu, mx0, 2));
        mx1 = fmaxf(mx1, __shfl_xor_sync(0xffffffffu, mx1, 1));
        mx1 = fmaxf(mx1, __shfl_xor_sync(0xffffffffu, mx1, 2));
        float nm0 = fmaxf(m0, mx0), nm1 = fmaxf(m1, mx1);
        float a0 = __expf(m0 - nm0), a1 = __expf(m1 - nm1);

        float sum0 = 0.0f, sum1 = 0.0f;
        int pr0 = warp * 16 + (lane >> 2);
        int pc0 = (lane & 3) * 2;
#pragma unroll
        for (int nt = 0; nt < 8; nt++) {
            float e00 = __expf(s[nt][0] - nm0);
            float e01 = __expf(s[nt][1] - nm0);
            float e10 = __expf(s[nt][2] - nm1);
            float e11 = __expf(s[nt][3] - nm1);
            sum0 += e00 + e01;
            sum1 += e10 + e11;
            *(__nv_bfloat162*)(smP + pr0 * APH + nt * 8 + pc0)       = __floats2bfloat162_rn(e00, e01);
            *(__nv_bfloat162*)(smP + (pr0 + 8) * APH + nt * 8 + pc0) = __floats2bfloat162_rn(e10, e11);
        }
        sum0 += __shfl_xor_sync(0xffffffffu, sum0, 1);
        sum0 += __shfl_xor_sync(0xffffffffu, sum0, 2);
        sum1 += __shfl_xor_sync(0xffffffffu, sum1, 1);
        sum1 += __shfl_xor_sync(0xffffffffu, sum1, 2);
        l0 = l0 * a0 + sum0;
        l1 = l1 * a1 + sum1;
        m0 = nm0; m1 = nm1;
#pragma unroll
        for (int nt = 0; nt < 8; nt++) {
            o[nt][0] *= a0; o[nt][1] *= a0;
            o[nt][2] *= a1; o[nt][3] *= a1;
        }
        __syncwarp();

        // O += P @ V : V is [key][d]; ldmatrix.trans yields V^T fragments.
#pragma unroll
        for (int j = 0; j < 4; j++) {
            uint32_t aF[4];
            LDSM4(aF[0], aF[1], aF[2], aF[3],
                  sP + (warp * 16 + laneA_r) * APB + (laneA_g + 2 * j) * 16);
            uint32_t tF[4][4];
#pragma unroll
            for (int pr = 0; pr < 4; pr++) {   // d16 pair
                uint32_t addr = vSt + (j * 16 + laneV_key) * APB
                                    + (pr * 16 + laneV_doff) * 2;
                LDSM4T(tF[pr][0], tF[pr][1], tF[pr][2], tF[pr][3], addr);
            }
#pragma unroll
            for (int nt = 0; nt < 8; nt++)
                MMA_BF16(o[nt], aF, tF[nt >> 1][(nt & 1) * 2], tF[nt >> 1][(nt & 1) * 2 + 1]);
        }
        // no trailing barrier: 3-stage ring; next refill of this stage is
        // fenced by the top-of-loop __syncthreads two iterations later.
    }

    // Epilogue: normalize, convert bf16
    float inv0 = 1.0f / l0, inv1 = 1.0f / l1;
    int r0 = qt * 128 + warp * 16 + (lane >> 2);
    int c0 = (lane & 3) * 2;
#pragma unroll
    for (int nt = 0; nt < 8; nt++) {
        size_t p0 = base + (size_t)r0 * D_MODEL + nt * 8 + c0;
        size_t p1 = base + (size_t)(r0 + 8) * D_MODEL + nt * 8 + c0;
        *(__nv_bfloat162*)(Og + p0) = __floats2bfloat162_rn(o[nt][0] * inv0, o[nt][1] * inv0);
        *(__nv_bfloat162*)(Og + p1) = __floats2bfloat162_rn(o[nt][2] * inv1, o[nt][3] * inv1);
    }
}

// ---------------------------------------------------------------------------
// LayerNorm
// ---------------------------------------------------------------------------
__global__ __launch_bounds__(256)
void ln_kernel(const float* __restrict__ X,
               const float* __restrict__ gamma,
               const float* __restrict__ beta,
               float* __restrict__ out)
{
    const int row = blockIdx.x;
    const int tid = threadIdx.x;
    const float* x = X + (size_t)row * D_MODEL;

    float4 f = *(const float4*)(x + tid * 4);
    float s  = f.x + f.y + f.z + f.w;
    float ss = f.x * f.x + f.y * f.y + f.z * f.z + f.w * f.w;

#pragma unroll
    for (int o = 16; o > 0; o >>= 1) {
        s  += __shfl_xor_sync(0xffffffffu, s,  o);
        ss += __shfl_xor_sync(0xffffffffu, ss, o);
    }

    __shared__ float sh[16];
    const int warp = tid >> 5, lane = tid & 31;
    if (lane == 0) { sh[warp] = s; sh[warp + 8] = ss; }
    __syncthreads();
    if (tid == 0) {
        float S = 0.0f, SS = 0.0f;
#pragma unroll
        for (int w = 0; w < 8; w++) { S += sh[w]; SS += sh[w + 8]; }
        float mu  = S * (1.0f / D_MODEL);
        float var = SS * (1.0f / D_MODEL) - mu * mu;
        sh[0] = mu;
        sh[1] = rsqrtf(var + LN_EPS);
    }
    __syncthreads();
    float mu = sh[0], rstd = sh[1];

    float4 gm = *(const float4*)(gamma + tid * 4);
    float4 bt = *(const float4*)(beta  + tid * 4);
    float4 o4;
    o4.x = (f.x - mu) * rstd * gm.x + bt.x;
    o4.y = (f.y - mu) * rstd * gm.y + bt.y;
    o4.z = (f.z - mu) * rstd * gm.z + bt.z;
    o4.w = (f.w - mu) * rstd * gm.w + bt.w;
    *(float4*)(out + (size_t)row * D_MODEL + tid * 4) = o4;
}

// ---------------------------------------------------------------------------
// Launch
// ---------------------------------------------------------------------------
extern "C" void kernel_launch(void* const* d_in, const int* in_sizes, int n_in,
                              void* d_out, int out_size)
{
    const float* batch = (const float*)d_in[0];
    const float* wq    = (const float*)d_in[1];
    const float* bq    = (const float*)d_in[2];
    const float* wk    = (const float*)d_in[3];
    const float* bk    = (const float*)d_in[4];
    const float* wv    = (const float*)d_in[5];
    const float* bv    = (const float*)d_in[6];
    const float* wo    = (const float*)d_in[7];
    const float* bo    = (const float*)d_in[8];
    const float* ln_g  = (const float*)d_in[9];
    const float* ln_b  = (const float*)d_in[10];

    __nv_bfloat16 *qh, *kh, *vh, *ah, *bxh, *wqkvh, *woh;
    float *x;
    cudaGetSymbolAddress((void**)&qh,    g_qh);
    cudaGetSymbolAddress((void**)&kh,    g_kh);
    cudaGetSymbolAddress((void**)&vh,    g_vh);
    cudaGetSymbolAddress((void**)&ah,    g_ah);
    cudaGetSymbolAddress((void**)&bxh,   g_bxh);
    cudaGetSymbolAddress((void**)&wqkvh, g_wqkv);
    cudaGetSymbolAddress((void**)&woh,   g_woh);
    cudaGetSymbolAddress((void**)&x,     g_x);

    static bool attr_done = false;
    if (!attr_done) {
        cudaFuncSetAttribute(gemm_bf16<0>, cudaFuncAttributeMaxDynamicSharedMemorySize, GSM);
        cudaFuncSetAttribute(gemm_bf16<1>, cudaFuncAttributeMaxDynamicSharedMemorySize, GSM);
        cudaFuncSetAttribute(attn_bf16, cudaFuncAttributeMaxDynamicSharedMemorySize, ASM_TOTAL);
        attr_done = true;
    }

    // fp32 -> bf16 conversions (3 launches)
    const int nb4 = MTOT * D_MODEL / 4;
    const int nw4 = D_MODEL * D_MODEL / 4;
    conv_bf16_kernel<<<(nb4 + 255) / 256, 256>>>(batch, bxh, nb4);
    conv_wqkv_kernel<<<(3 * nw4 + 255) / 256, 256>>>(wq, wk, wv, wqkvh);
    conv_bf16_kernel<<<(nw4 + 255) / 256, 256>>>(wo, woh, nw4);

    // Fused QKV projection: [8192,1024] @ [3072,1024]^T
    dim3 gq(3 * D_MODEL / 128, MTOT / 128);  // (24, 64)
    gemm_bf16<0><<<gq, 256, GSM>>>(bxh, wqkvh, bq, bk, bv, qh, kh, vh,
                                   nullptr, nullptr, MTOT, D_MODEL);

    dim3 ga(SEQ / 128, NHEAD, BATCH);        // (16, 16, 4)
    attn_bf16<<<ga, 256, ASM_TOTAL>>>(qh, kh, vh, ah);

    // Out-projection + residual (fp32 out)
    dim3 gg(D_MODEL / 128, MTOT / 128);      // (8, 64)
    gemm_bf16<1><<<gg, 256, GSM>>>(ah, woh, bo, nullptr, nullptr,
                                   nullptr, nullptr, nullptr, batch, x,
                                   MTOT, D_MODEL);

    ln_kernel<<<MTOT, 256>>>(x, ln_g, ln_b, (float*)d_out);
}

// round 9
// speedup vs baseline: 10.6570x; 1.0728x over previous
#include <cuda_runtime.h>
#include <cuda_bf16.h>
#include <cstdint>

#define D_MODEL 1024
#define SEQ     2048
#define BATCH   4
#define NHEAD   16
#define DHEAD   64
#define MTOT    (BATCH*SEQ)   // 8192
#define LN_EPS  1e-5f

// ---------------------------------------------------------------------------
// Scratch (no cudaMalloc allowed). bf16 operands, fp32 where accuracy matters.
// ---------------------------------------------------------------------------
__device__ __nv_bfloat16 g_qh[(size_t)MTOT * D_MODEL];
__device__ __nv_bfloat16 g_kh[(size_t)MTOT * D_MODEL];
__device__ __nv_bfloat16 g_vh[(size_t)MTOT * D_MODEL];
__device__ __nv_bfloat16 g_ah[(size_t)MTOT * D_MODEL];   // attention output
__device__ __nv_bfloat16 g_bxh[(size_t)MTOT * D_MODEL];  // bf16 batch
__device__ __nv_bfloat16 g_wqkv[(size_t)3 * D_MODEL * D_MODEL]; // packed q,k,v
__device__ __nv_bfloat16 g_woh[(size_t)D_MODEL * D_MODEL];
__device__ float g_x[(size_t)MTOT * D_MODEL];            // residual sum (fp32)

// ---------------------------------------------------------------------------
// Helpers
// ---------------------------------------------------------------------------
__device__ __forceinline__ uint32_t s2u(const void* p) {
    uint32_t a;
    asm("{ .reg .u64 t; cvta.to.shared.u64 t, %1; cvt.u32.u64 %0, t; }"
        : "=r"(a) : "l"(p));
    return a;
}

#define LDSM4(f0,f1,f2,f3,addr) \
    asm volatile("ldmatrix.sync.aligned.m8n8.x4.shared.b16 {%0,%1,%2,%3}, [%4];" \
                 : "=r"(f0), "=r"(f1), "=r"(f2), "=r"(f3) : "r"(addr))

#define LDSM4T(f0,f1,f2,f3,addr) \
    asm volatile("ldmatrix.sync.aligned.m8n8.x4.trans.shared.b16 {%0,%1,%2,%3}, [%4];" \
                 : "=r"(f0), "=r"(f1), "=r"(f2), "=r"(f3) : "r"(addr))

#define MMA_BF16(d, a, b0, b1) \
    asm volatile("mma.sync.aligned.m16n8k16.row.col.f32.bf16.bf16.f32 " \
                 "{%0,%1,%2,%3}, {%4,%5,%6,%7}, {%8,%9}, {%0,%1,%2,%3};" \
                 : "+f"((d)[0]), "+f"((d)[1]), "+f"((d)[2]), "+f"((d)[3]) \
                 : "r"((a)[0]), "r"((a)[1]), "r"((a)[2]), "r"((a)[3]), \
                   "r"(b0), "r"(b1))

#define CP16(dst, src) \
    asm volatile("cp.async.cg.shared.global [%0], [%1], 16;" \
                 :: "r"(dst), "l"(src) : "memory")

__device__ __forceinline__ uint32_t packbf(float a, float b) {
    __nv_bfloat162 h = __floats2bfloat162_rn(a, b);
    return *(uint32_t*)&h;
}

// ---------------------------------------------------------------------------
// fp32 -> bf16 (rn) conversions
// ---------------------------------------------------------------------------
__global__ __launch_bounds__(256)
void conv_bf16_kernel(const float* __restrict__ in, __nv_bfloat16* __restrict__ out, int n4)
{
    int i = blockIdx.x * blockDim.x + threadIdx.x;
    if (i < n4) {
        float4 f = ((const float4*)in)[i];
        ((__nv_bfloat162*)out)[i * 2]     = __floats2bfloat162_rn(f.x, f.y);
        ((__nv_bfloat162*)out)[i * 2 + 1] = __floats2bfloat162_rn(f.z, f.w);
    }
}

// Pack wq, wk, wv -> g_wqkv [3072][1024] bf16
__global__ __launch_bounds__(256)
void conv_wqkv_kernel(const float* __restrict__ wq, const float* __restrict__ wk,
                      const float* __restrict__ wv, __nv_bfloat16* __restrict__ out)
{
    const int per = (D_MODEL * D_MODEL) / 4;
    int i = blockIdx.x * blockDim.x + threadIdx.x;
    if (i < 3 * per) {
        int w = i / per, j = i - w * per;
        const float* src = (w == 0) ? wq : (w == 1) ? wk : wv;
        float4 f = ((const float4*)src)[j];
        __nv_bfloat162* dst = (__nv_bfloat162*)(out + (size_t)w * D_MODEL * D_MODEL);
        dst[j * 2]     = __floats2bfloat162_rn(f.x, f.y);
        dst[j * 2 + 1] = __floats2bfloat162_rn(f.z, f.w);
    }
}

// ---------------------------------------------------------------------------
// bf16 mma GEMM. MODE 0: fused QKV. MODE 1: out-proj (fp32 out + residual).
// CTA tile 128x128, 128 threads = 4 warps, warp tile 64x64 (2x2 warp grid).
// BK=64 halves, NS=3 cp.async stages, one __syncthreads per chunk.
// Smem row pitch 72 halves (144B): 8-row ldmatrix phases conflict-free.
// ---------------------------------------------------------------------------
#define GPH   72                    // halves per smem row (64 data + 8 pad)
#define GSTGB (128 * GPH * 2)       // 18432 bytes per operand per stage
#define GSM   (3 * 2 * GSTGB)       // 110592 bytes dynamic smem

template<int MODE>
__global__ __launch_bounds__(128, 2)
void gemm_bf16(const __nv_bfloat16* __restrict__ A, const __nv_bfloat16* __restrict__ W,
               const float* __restrict__ b0p, const float* __restrict__ b1p,
               const float* __restrict__ b2p,
               __nv_bfloat16* __restrict__ o0p, __nv_bfloat16* __restrict__ o1p,
               __nv_bfloat16* __restrict__ o2p,
               const float* __restrict__ resid, float* __restrict__ Cf,
               int M, int K)
{
    extern __shared__ __align__(16) char gsm[];
    const uint32_t sA = s2u(gsm);
    const uint32_t sB = sA + 3 * GSTGB;

    const int tid  = threadIdx.x;
    const int wid  = tid >> 5;
    const int lane = tid & 31;
    const int wm   = wid & 1;        // 0..1 (m-64 half)
    const int wn   = wid >> 1;       // 0..1 (n-64 half)
    const int m0   = blockIdx.y * 128;
    const int n0   = blockIdx.x * 128;
    const int NCH  = K / 64;               // 16

    // Output routing
    const float* bias;
    __nv_bfloat16* Cb = nullptr;
    int nloc0;
    if (MODE == 0) {
        int seg = n0 >> 10;
        bias  = (seg == 0) ? b0p : (seg == 1) ? b1p : b2p;
        Cb    = (seg == 0) ? o0p : (seg == 1) ? o1p : o2p;
        nloc0 = n0 & 1023;
    } else {
        bias  = b0p;
        nloc0 = n0;
    }

    const int r_ld = tid >> 3;       // 0..15 base row
    const int g_ld = tid & 7;        // 16B granule (8 halves)
    const __nv_bfloat16* Abase = A + (size_t)m0 * K + g_ld * 8;
    const __nv_bfloat16* Wbase = W + (size_t)n0 * K + g_ld * 8;

    auto issue = [&](int c) {
        if (c < NCH) {
            int st = c - (c / 3) * 3;
            uint32_t da = sA + st * GSTGB;
            uint32_t db = sB + st * GSTGB;
            long ko = (long)c * 64;
#pragma unroll
            for (int q = 0; q < 8; q++) {
                int row = r_ld + q * 16;
                CP16(da + row * (GPH * 2) + g_ld * 16, Abase + (size_t)row * K + ko);
                CP16(db + row * (GPH * 2) + g_ld * 16, Wbase + (size_t)row * K + ko);
            }
        }
        asm volatile("cp.async.commit_group;" ::: "memory");
    };

    float acc[4][8][4];
#pragma unroll
    for (int i = 0; i < 4; i++)
#pragma unroll
        for (int j = 0; j < 8; j++)
#pragma unroll
            for (int k = 0; k < 4; k++) acc[i][j][k] = 0.0f;

    const int laneA_r = ((lane >> 3) & 1) * 8 + (lane & 7);
    const int laneA_g = lane >> 4;
    const int laneB_r = (lane >> 4) * 8 + (lane & 7);
    const int laneB_g = (lane >> 3) & 1;

    issue(0); issue(1);

    for (int c = 0; c < NCH; c++) {
        asm volatile("cp.async.wait_group 1;" ::: "memory");
        __syncthreads();
        issue(c + 2);

        int st = c - (c / 3) * 3;
        uint32_t aSt = sA + st * GSTGB;
        uint32_t bSt = sB + st * GSTGB;

#pragma unroll
        for (int j = 0; j < 4; j++) {          // four k16 steps per BK=64
            uint32_t aF[4][4], bF[4][4];
#pragma unroll
            for (int mt = 0; mt < 4; mt++) {
                uint32_t addr = aSt + (wm * 64 + mt * 16 + laneA_r) * (GPH * 2)
                                    + (laneA_g + 2 * j) * 16;
                LDSM4(aF[mt][0], aF[mt][1], aF[mt][2], aF[mt][3], addr);
            }
#pragma unroll
            for (int np = 0; np < 4; np++) {
                uint32_t addr = bSt + (wn * 64 + np * 16 + laneB_r) * (GPH * 2)
                                    + (laneB_g + 2 * j) * 16;
                LDSM4(bF[np][0], bF[np][1], bF[np][2], bF[np][3], addr);
            }
#pragma unroll
            for (int mt = 0; mt < 4; mt++) {
#pragma unroll
                for (int nt = 0; nt < 8; nt++) {
                    MMA_BF16(acc[mt][nt], aF[mt],
                             bF[nt >> 1][(nt & 1) * 2], bF[nt >> 1][(nt & 1) * 2 + 1]);
                }
            }
        }
    }

    // Epilogue (output row stride is always 1024)
    const int rb = lane >> 2;
    const int cb = (lane & 3) * 2;
#pragma unroll
    for (int mt = 0; mt < 4; mt++) {
#pragma unroll
        for (int nt = 0; nt < 8; nt++) {
            int nl = nloc0 + wn * 64 + nt * 8 + cb;
            float2 bv = *(const float2*)(bias + nl);
            int row0 = m0 + wm * 64 + mt * 16 + rb;
            int row1 = row0 + 8;
            float v00 = acc[mt][nt][0] + bv.x;
            float v01 = acc[mt][nt][1] + bv.y;
            float v10 = acc[mt][nt][2] + bv.x;
            float v11 = acc[mt][nt][3] + bv.y;
            if (MODE == 0) {
                *(__nv_bfloat162*)(Cb + (size_t)row0 * D_MODEL + nl) = __floats2bfloat162_rn(v00, v01);
                *(__nv_bfloat162*)(Cb + (size_t)row1 * D_MODEL + nl) = __floats2bfloat162_rn(v10, v11);
            } else {
                float2 r0 = *(const float2*)(resid + (size_t)row0 * D_MODEL + nl);
                float2 r1 = *(const float2*)(resid + (size_t)row1 * D_MODEL + nl);
                *(float2*)(Cf + (size_t)row0 * D_MODEL + nl) = make_float2(v00 + r0.x, v01 + r0.y);
                *(float2*)(Cf + (size_t)row1 * D_MODEL + nl) = make_float2(v10 + r1.x, v11 + r1.y);
            }
        }
    }
}

// ---------------------------------------------------------------------------
// bf16 tensor-core flash attention (fp32 accum + softmax).
// grid = (SEQ/128, NHEAD, BATCH) = (16,16,4); 256 threads = 8 warps.
// Warp w owns query rows 16w..16w+15. K tiles of 64 keys.
// Q fragments hoisted to registers (loaded once). P fragments built by
// bf16-packing the S accumulators in registers (C->A fragment layout match):
// no P smem round-trip. 3-stage cp.async K/V ring, one barrier per tile.
// Smem: sK[3][64][72] | sV[3][64][72] | sQ[128][72] = 72 KB.
// ---------------------------------------------------------------------------
#define APH    72
#define APB    (APH * 2)            // 144 bytes row pitch
#define KSTG   (64 * APB)           // 9216 per stage
#define AOFF_K  0
#define AOFF_V  (3 * KSTG)           // 27648
#define AOFF_Q  (6 * KSTG)           // 55296
#define ASM_TOTAL (AOFF_Q + 128 * APB) // 73728

__global__ __launch_bounds__(256, 2)
void attn_bf16(const __nv_bfloat16* __restrict__ Q,
               const __nv_bfloat16* __restrict__ Kg,
               const __nv_bfloat16* __restrict__ Vg,
               __nv_bfloat16* __restrict__ Og)
{
    extern __shared__ __align__(16) char asmem[];
    const uint32_t sb = s2u(asmem);
    const uint32_t sK = sb + AOFF_K;
    const uint32_t sV = sb + AOFF_V;
    const uint32_t sQ = sb + AOFF_Q;
    __nv_bfloat16* smQ = (__nv_bfloat16*)(asmem + AOFF_Q);

    const int qt   = blockIdx.x;
    const int h    = blockIdx.y;
    const int b    = blockIdx.z;
    const int tid  = threadIdx.x;
    const int warp = tid >> 5;
    const int lane = tid & 31;

    const size_t base = ((size_t)b * SEQ) * D_MODEL + (size_t)h * DHEAD;
    const int NT = SEQ / 64;  // 32

    auto issue_kv = [&](int kt) {
        if (kt < NT) {
            int st = kt - (kt / 3) * 3;
            uint32_t kd = sK + st * KSTG;
            uint32_t vd = sV + st * KSTG;
            const __nv_bfloat16* kp = Kg + base + (size_t)(kt * 64) * D_MODEL;
            const __nv_bfloat16* vp = Vg + base + (size_t)(kt * 64) * D_MODEL;
#pragma unroll
            for (int q = 0; q < 2; q++) {
                int id = tid + q * 256;
                int r = id >> 3, g = id & 7;
                CP16(kd + r * APB + g * 16, kp + (size_t)r * D_MODEL + g * 8);
                CP16(vd + r * APB + g * 16, vp + (size_t)r * D_MODEL + g * 8);
            }
        }
        asm volatile("cp.async.commit_group;" ::: "memory");
    };

    issue_kv(0);
    issue_kv(1);

    // Load Q tile (128 x 64 halves) into smem, then hoist fragments.
    for (int i = tid; i < 1024; i += 256) {
        int r = i >> 3;
        int g = i & 7;
        uint4 f = *(const uint4*)(Q + base + (size_t)(qt * 128 + r) * D_MODEL + g * 8);
        *(uint4*)(smQ + r * APH + g * 8) = f;
    }
    __syncthreads();

    const int laneA_r = ((lane >> 3) & 1) * 8 + (lane & 7);
    const int laneA_g = lane >> 4;
    const int laneB_r = (lane >> 4) * 8 + (lane & 7);
    const int laneB_g = (lane >> 3) & 1;
    const int laneV_key  = ((lane >> 3) & 1) * 8 + (lane & 7);
    const int laneV_doff = (lane >> 4) * 8;

    uint32_t qF[4][4];
#pragma unroll
    for (int j = 0; j < 4; j++) {
        LDSM4(qF[j][0], qF[j][1], qF[j][2], qF[j][3],
              sQ + (warp * 16 + laneA_r) * APB + (laneA_g + 2 * j) * 16);
    }

    float m0 = -1e30f, m1 = -1e30f, l0 = 0.0f, l1 = 0.0f;
    float o[8][4];
#pragma unroll
    for (int nt = 0; nt < 8; nt++)
#pragma unroll
        for (int i = 0; i < 4; i++) o[nt][i] = 0.0f;

    for (int kt = 0; kt < NT; kt++) {
        asm volatile("cp.async.wait_group 1;" ::: "memory");
        __syncthreads();       // all warps done with the stage being refilled
        issue_kv(kt + 2);

        int st = kt - (kt / 3) * 3;
        uint32_t kSt = sK + st * KSTG;
        uint32_t vSt = sV + st * KSTG;

        // S = Q @ K^T  (4 k16 steps over d=64; 8 n8-tiles over 64 keys)
        float s[8][4];
#pragma unroll
        for (int nt = 0; nt < 8; nt++)
#pragma unroll
            for (int i = 0; i < 4; i++) s[nt][i] = 0.0f;

#pragma unroll
        for (int j = 0; j < 4; j++) {
            uint32_t bF[4][4];
#pragma unroll
            for (int np = 0; np < 4; np++) {
                LDSM4(bF[np][0], bF[np][1], bF[np][2], bF[np][3],
                      kSt + (np * 16 + laneB_r) * APB + (laneB_g + 2 * j) * 16);
            }
#pragma unroll
            for (int nt = 0; nt < 8; nt++)
                MMA_BF16(s[nt], qF[j], bF[nt >> 1][(nt & 1) * 2], bF[nt >> 1][(nt & 1) * 2 + 1]);
        }

        // scale + online softmax (rows r0 and r0+8 of warp's m16)
        float mx0 = -1e30f, mx1 = -1e30f;
#pragma unroll
        for (int nt = 0; nt < 8; nt++) {
            s[nt][0] *= 0.125f; s[nt][1] *= 0.125f;
            s[nt][2] *= 0.125f; s[nt][3] *= 0.125f;
            mx0 = fmaxf(mx0, fmaxf(s[nt][0], s[nt][1]));
            mx1 = fmaxf(mx1, fmaxf(s[nt][2], s[nt][3]));
        }
        mx0 = fmaxf(mx0, __shfl_xor_sync(0xffffffffu, mx0, 1));
        mx0 = fmaxf(mx0, __shfl_xor_sync(0xffffffffu, mx0, 2));
        mx1 = fmaxf(mx1, __shfl_xor_sync(0xffffffffu, mx1, 1));
        mx1 = fmaxf(mx1, __shfl_xor_sync(0xffffffffu, mx1, 2));
        float nm0 = fmaxf(m0, mx0), nm1 = fmaxf(m1, mx1);
        float a0 = __expf(m0 - nm0), a1 = __expf(m1 - nm1);

        float sum0 = 0.0f, sum1 = 0.0f;
#pragma unroll
        for (int nt = 0; nt < 8; nt++) {
            s[nt][0] = __expf(s[nt][0] - nm0);
            s[nt][1] = __expf(s[nt][1] - nm0);
            s[nt][2] = __expf(s[nt][2] - nm1);
            s[nt][3] = __expf(s[nt][3] - nm1);
            sum0 += s[nt][0] + s[nt][1];
            sum1 += s[nt][2] + s[nt][3];
        }
        sum0 += __shfl_xor_sync(0xffffffffu, sum0, 1);
        sum0 += __shfl_xor_sync(0xffffffffu, sum0, 2);
        sum1 += __shfl_xor_sync(0xffffffffu, sum1, 1);
        sum1 += __shfl_xor_sync(0xffffffffu, sum1, 2);
        l0 = l0 * a0 + sum0;
        l1 = l1 * a1 + sum1;
        m0 = nm0; m1 = nm1;
#pragma unroll
        for (int nt = 0; nt < 8; nt++) {
            o[nt][0] *= a0; o[nt][1] *= a0;
            o[nt][2] *= a1; o[nt][3] *= a1;
        }

        // Build P A-fragments in registers: C(m16n8)x2 -> A(m16k16) layout.
        uint32_t pA[4][4];
#pragma unroll
        for (int j = 0; j < 4; j++) {
            pA[j][0] = packbf(s[2*j][0],   s[2*j][1]);
            pA[j][1] = packbf(s[2*j][2],   s[2*j][3]);
            pA[j][2] = packbf(s[2*j+1][0], s[2*j+1][1]);
            pA[j][3] = packbf(s[2*j+1][2], s[2*j+1][3]);
        }

        // O += P @ V : V is [key][d]; ldmatrix.trans yields V^T fragments.
#pragma unroll
        for (int j = 0; j < 4; j++) {
            uint32_t tF[4][4];
#pragma unroll
            for (int pr = 0; pr < 4; pr++) {   // d16 pair
                uint32_t addr = vSt + (j * 16 + laneV_key) * APB
                                    + (pr * 16 + laneV_doff) * 2;
                LDSM4T(tF[pr][0], tF[pr][1], tF[pr][2], tF[pr][3], addr);
            }
#pragma unroll
            for (int nt = 0; nt < 8; nt++)
                MMA_BF16(o[nt], pA[j], tF[nt >> 1][(nt & 1) * 2], tF[nt >> 1][(nt & 1) * 2 + 1]);
        }
        // no trailing barrier: 3-stage ring; next refill of this stage is
        // fenced by the top-of-loop __syncthreads two iterations later.
    }

    // Epilogue: normalize, convert bf16
    float inv0 = 1.0f / l0, inv1 = 1.0f / l1;
    int r0 = qt * 128 + warp * 16 + (lane >> 2);
    int c0 = (lane & 3) * 2;
#pragma unroll
    for (int nt = 0; nt < 8; nt++) {
        size_t p0 = base + (size_t)r0 * D_MODEL + nt * 8 + c0;
        size_t p1 = base + (size_t)(r0 + 8) * D_MODEL + nt * 8 + c0;
        *(__nv_bfloat162*)(Og + p0) = __floats2bfloat162_rn(o[nt][0] * inv0, o[nt][1] * inv0);
        *(__nv_bfloat162*)(Og + p1) = __floats2bfloat162_rn(o[nt][2] * inv1, o[nt][3] * inv1);
    }
}

// ---------------------------------------------------------------------------
// LayerNorm
// ---------------------------------------------------------------------------
__global__ __launch_bounds__(256)
void ln_kernel(const float* __restrict__ X,
               const float* __restrict__ gamma,
               const float* __restrict__ beta,
               float* __restrict__ out)
{
    const int row = blockIdx.x;
    const int tid = threadIdx.x;
    const float* x = X + (size_t)row * D_MODEL;

    float4 f = *(const float4*)(x + tid * 4);
    float s  = f.x + f.y + f.z + f.w;
    float ss = f.x * f.x + f.y * f.y + f.z * f.z + f.w * f.w;

#pragma unroll
    for (int o = 16; o > 0; o >>= 1) {
        s  += __shfl_xor_sync(0xffffffffu, s,  o);
        ss += __shfl_xor_sync(0xffffffffu, ss, o);
    }

    __shared__ float sh[16];
    const int warp = tid >> 5, lane = tid & 31;
    if (lane == 0) { sh[warp] = s; sh[warp + 8] = ss; }
    __syncthreads();
    if (tid == 0) {
        float S = 0.0f, SS = 0.0f;
#pragma unroll
        for (int w = 0; w < 8; w++) { S += sh[w]; SS += sh[w + 8]; }
        float mu  = S * (1.0f / D_MODEL);
        float var = SS * (1.0f / D_MODEL) - mu * mu;
        sh[0] = mu;
        sh[1] = rsqrtf(var + LN_EPS);
    }
    __syncthreads();
    float mu = sh[0], rstd = sh[1];

    float4 gm = *(const float4*)(gamma + tid * 4);
    float4 bt = *(const float4*)(beta  + tid * 4);
    float4 o4;
    o4.x = (f.x - mu) * rstd * gm.x + bt.x;
    o4.y = (f.y - mu) * rstd * gm.y + bt.y;
    o4.z = (f.z - mu) * rstd * gm.z + bt.z;
    o4.w = (f.w - mu) * rstd * gm.w + bt.w;
    *(float4*)(out + (size_t)row * D_MODEL + tid * 4) = o4;
}

// ---------------------------------------------------------------------------
// Launch
// ---------------------------------------------------------------------------
extern "C" void kernel_launch(void* const* d_in, const int* in_sizes, int n_in,
                              void* d_out, int out_size)
{
    const float* batch = (const float*)d_in[0];
    const float* wq    = (const float*)d_in[1];
    const float* bq    = (const float*)d_in[2];
    const float* wk    = (const float*)d_in[3];
    const float* bk    = (const float*)d_in[4];
    const float* wv    = (const float*)d_in[5];
    const float* bv    = (const float*)d_in[6];
    const float* wo    = (const float*)d_in[7];
    const float* bo    = (const float*)d_in[8];
    const float* ln_g  = (const float*)d_in[9];
    const float* ln_b  = (const float*)d_in[10];

    __nv_bfloat16 *qh, *kh, *vh, *ah, *bxh, *wqkvh, *woh;
    float *x;
    cudaGetSymbolAddress((void**)&qh,    g_qh);
    cudaGetSymbolAddress((void**)&kh,    g_kh);
    cudaGetSymbolAddress((void**)&vh,    g_vh);
    cudaGetSymbolAddress((void**)&ah,    g_ah);
    cudaGetSymbolAddress((void**)&bxh,   g_bxh);
    cudaGetSymbolAddress((void**)&wqkvh, g_wqkv);
    cudaGetSymbolAddress((void**)&woh,   g_woh);
    cudaGetSymbolAddress((void**)&x,     g_x);

    static bool attr_done = false;
    if (!attr_done) {
        cudaFuncSetAttribute(gemm_bf16<0>, cudaFuncAttributeMaxDynamicSharedMemorySize, GSM);
        cudaFuncSetAttribute(gemm_bf16<1>, cudaFuncAttributeMaxDynamicSharedMemorySize, GSM);
        cudaFuncSetAttribute(attn_bf16, cudaFuncAttributeMaxDynamicSharedMemorySize, ASM_TOTAL);
        attr_done = true;
    }

    // fp32 -> bf16 conversions (3 launches)
    const int nb4 = MTOT * D_MODEL / 4;
    const int nw4 = D_MODEL * D_MODEL / 4;
    conv_bf16_kernel<<<(nb4 + 255) / 256, 256>>>(batch, bxh, nb4);
    conv_wqkv_kernel<<<(3 * nw4 + 255) / 256, 256>>>(wq, wk, wv, wqkvh);
    conv_bf16_kernel<<<(nw4 + 255) / 256, 256>>>(wo, woh, nw4);

    // Fused QKV projection: [8192,1024] @ [3072,1024]^T
    dim3 gq(3 * D_MODEL / 128, MTOT / 128);  // (24, 64)
    gemm_bf16<0><<<gq, 128, GSM>>>(bxh, wqkvh, bq, bk, bv, qh, kh, vh,
                                   nullptr, nullptr, MTOT, D_MODEL);

    dim3 ga(SEQ / 128, NHEAD, BATCH);        // (16, 16, 4)
    attn_bf16<<<ga, 256, ASM_TOTAL>>>(qh, kh, vh, ah);

    // Out-projection + residual (fp32 out)
    dim3 gg(D_MODEL / 128, MTOT / 128);      // (8, 64)
    gemm_bf16<1><<<gg, 128, GSM>>>(ah, woh, bo, nullptr, nullptr,
                                   nullptr, nullptr, nullptr, batch, x,
                                   MTOT, D_MODEL);

    ln_kernel<<<MTOT, 256>>>(x, ln_g, ln_b, (float*)d_out);
}

// round 10
// speedup vs baseline: 10.9723x; 1.0296x over previous
#include <cuda_runtime.h>
#include <cuda_bf16.h>
#include <cstdint>

#define D_MODEL 1024
#define SEQ     2048
#define BATCH   4
#define NHEAD   16
#define DHEAD   64
#define MTOT    (BATCH*SEQ)   // 8192
#define LN_EPS  1e-5f

// ---------------------------------------------------------------------------
// Scratch (no cudaMalloc allowed). bf16 operands, fp32 where accuracy matters.
// ---------------------------------------------------------------------------
__device__ __nv_bfloat16 g_qh[(size_t)MTOT * D_MODEL];
__device__ __nv_bfloat16 g_kh[(size_t)MTOT * D_MODEL];
__device__ __nv_bfloat16 g_vh[(size_t)MTOT * D_MODEL];
__device__ __nv_bfloat16 g_ah[(size_t)MTOT * D_MODEL];   // attention output
__device__ __nv_bfloat16 g_bxh[(size_t)MTOT * D_MODEL];  // bf16 batch
__device__ __nv_bfloat16 g_wqkv[(size_t)3 * D_MODEL * D_MODEL]; // packed q,k,v
__device__ __nv_bfloat16 g_woh[(size_t)D_MODEL * D_MODEL];
__device__ float g_x[(size_t)MTOT * D_MODEL];            // residual sum (fp32)

// ---------------------------------------------------------------------------
// Helpers
// ---------------------------------------------------------------------------
__device__ __forceinline__ uint32_t s2u(const void* p) {
    uint32_t a;
    asm("{ .reg .u64 t; cvta.to.shared.u64 t, %1; cvt.u32.u64 %0, t; }"
        : "=r"(a) : "l"(p));
    return a;
}

#define LDSM4(f0,f1,f2,f3,addr) \
    asm volatile("ldmatrix.sync.aligned.m8n8.x4.shared.b16 {%0,%1,%2,%3}, [%4];" \
                 : "=r"(f0), "=r"(f1), "=r"(f2), "=r"(f3) : "r"(addr))

#define LDSM4T(f0,f1,f2,f3,addr) \
    asm volatile("ldmatrix.sync.aligned.m8n8.x4.trans.shared.b16 {%0,%1,%2,%3}, [%4];" \
                 : "=r"(f0), "=r"(f1), "=r"(f2), "=r"(f3) : "r"(addr))

#define MMA_BF16(d, a, b0, b1) \
    asm volatile("mma.sync.aligned.m16n8k16.row.col.f32.bf16.bf16.f32 " \
                 "{%0,%1,%2,%3}, {%4,%5,%6,%7}, {%8,%9}, {%0,%1,%2,%3};" \
                 : "+f"((d)[0]), "+f"((d)[1]), "+f"((d)[2]), "+f"((d)[3]) \
                 : "r"((a)[0]), "r"((a)[1]), "r"((a)[2]), "r"((a)[3]), \
                   "r"(b0), "r"(b1))

#define CP16(dst, src) \
    asm volatile("cp.async.cg.shared.global [%0], [%1], 16;" \
                 :: "r"(dst), "l"(src) : "memory")

__device__ __forceinline__ uint32_t packbf(float a, float b) {
    __nv_bfloat162 h = __floats2bfloat162_rn(a, b);
    return *(uint32_t*)&h;
}

// Raw MUFU exp2 (single EX2, no pre-multiply)
__device__ __forceinline__ float ex2(float x) {
    float r;
    asm("ex2.approx.f32 %0, %1;" : "=f"(r) : "f"(x));
    return r;
}

// ---------------------------------------------------------------------------
// fp32 -> bf16 (rn) conversions
// ---------------------------------------------------------------------------
__global__ __launch_bounds__(256)
void conv_bf16_kernel(const float* __restrict__ in, __nv_bfloat16* __restrict__ out, int n4)
{
    int i = blockIdx.x * blockDim.x + threadIdx.x;
    if (i < n4) {
        float4 f = ((const float4*)in)[i];
        ((__nv_bfloat162*)out)[i * 2]     = __floats2bfloat162_rn(f.x, f.y);
        ((__nv_bfloat162*)out)[i * 2 + 1] = __floats2bfloat162_rn(f.z, f.w);
    }
}

// Pack wq, wk, wv -> g_wqkv [3072][1024] bf16
__global__ __launch_bounds__(256)
void conv_wqkv_kernel(const float* __restrict__ wq, const float* __restrict__ wk,
                      const float* __restrict__ wv, __nv_bfloat16* __restrict__ out)
{
    const int per = (D_MODEL * D_MODEL) / 4;
    int i = blockIdx.x * blockDim.x + threadIdx.x;
    if (i < 3 * per) {
        int w = i / per, j = i - w * per;
        const float* src = (w == 0) ? wq : (w == 1) ? wk : wv;
        float4 f = ((const float4*)src)[j];
        __nv_bfloat162* dst = (__nv_bfloat162*)(out + (size_t)w * D_MODEL * D_MODEL);
        dst[j * 2]     = __floats2bfloat162_rn(f.x, f.y);
        dst[j * 2 + 1] = __floats2bfloat162_rn(f.z, f.w);
    }
}

// ---------------------------------------------------------------------------
// bf16 mma GEMM. MODE 0: fused QKV. MODE 1: out-proj (fp32 out + residual).
// CTA tile 128x128, 128 threads = 4 warps, warp tile 64x64 (2x2 warp grid).
// BK=64 halves, NS=3 cp.async stages, one __syncthreads per chunk.
// (unchanged from Round 9 — near the mma.sync HMMA ceiling)
// ---------------------------------------------------------------------------
#define GPH   72                    // halves per smem row (64 data + 8 pad)
#define GSTGB (128 * GPH * 2)       // 18432 bytes per operand per stage
#define GSM   (3 * 2 * GSTGB)       // 110592 bytes dynamic smem

template<int MODE>
__global__ __launch_bounds__(128, 2)
void gemm_bf16(const __nv_bfloat16* __restrict__ A, const __nv_bfloat16* __restrict__ W,
               const float* __restrict__ b0p, const float* __restrict__ b1p,
               const float* __restrict__ b2p,
               __nv_bfloat16* __restrict__ o0p, __nv_bfloat16* __restrict__ o1p,
               __nv_bfloat16* __restrict__ o2p,
               const float* __restrict__ resid, float* __restrict__ Cf,
               int M, int K)
{
    extern __shared__ __align__(16) char gsm[];
    const uint32_t sA = s2u(gsm);
    const uint32_t sB = sA + 3 * GSTGB;

    const int tid  = threadIdx.x;
    const int wid  = tid >> 5;
    const int lane = tid & 31;
    const int wm   = wid & 1;
    const int wn   = wid >> 1;
    const int m0   = blockIdx.y * 128;
    const int n0   = blockIdx.x * 128;
    const int NCH  = K / 64;               // 16

    const float* bias;
    __nv_bfloat16* Cb = nullptr;
    int nloc0;
    if (MODE == 0) {
        int seg = n0 >> 10;
        bias  = (seg == 0) ? b0p : (seg == 1) ? b1p : b2p;
        Cb    = (seg == 0) ? o0p : (seg == 1) ? o1p : o2p;
        nloc0 = n0 & 1023;
    } else {
        bias  = b0p;
        nloc0 = n0;
    }

    const int r_ld = tid >> 3;
    const int g_ld = tid & 7;
    const __nv_bfloat16* Abase = A + (size_t)m0 * K + g_ld * 8;
    const __nv_bfloat16* Wbase = W + (size_t)n0 * K + g_ld * 8;

    auto issue = [&](int c) {
        if (c < NCH) {
            int st = c - (c / 3) * 3;
            uint32_t da = sA + st * GSTGB;
            uint32_t db = sB + st * GSTGB;
            long ko = (long)c * 64;
#pragma unroll
            for (int q = 0; q < 8; q++) {
                int row = r_ld + q * 16;
                CP16(da + row * (GPH * 2) + g_ld * 16, Abase + (size_t)row * K + ko);
                CP16(db + row * (GPH * 2) + g_ld * 16, Wbase + (size_t)row * K + ko);
            }
        }
        asm volatile("cp.async.commit_group;" ::: "memory");
    };

    float acc[4][8][4];
#pragma unroll
    for (int i = 0; i < 4; i++)
#pragma unroll
        for (int j = 0; j < 8; j++)
#pragma unroll
            for (int k = 0; k < 4; k++) acc[i][j][k] = 0.0f;

    const int laneA_r = ((lane >> 3) & 1) * 8 + (lane & 7);
    const int laneA_g = lane >> 4;
    const int laneB_r = (lane >> 4) * 8 + (lane & 7);
    const int laneB_g = (lane >> 3) & 1;

    issue(0); issue(1);

    for (int c = 0; c < NCH; c++) {
        asm volatile("cp.async.wait_group 1;" ::: "memory");
        __syncthreads();
        issue(c + 2);

        int st = c - (c / 3) * 3;
        uint32_t aSt = sA + st * GSTGB;
        uint32_t bSt = sB + st * GSTGB;

#pragma unroll
        for (int j = 0; j < 4; j++) {
            uint32_t aF[4][4], bF[4][4];
#pragma unroll
            for (int mt = 0; mt < 4; mt++) {
                uint32_t addr = aSt + (wm * 64 + mt * 16 + laneA_r) * (GPH * 2)
                                    + (laneA_g + 2 * j) * 16;
                LDSM4(aF[mt][0], aF[mt][1], aF[mt][2], aF[mt][3], addr);
            }
#pragma unroll
            for (int np = 0; np < 4; np++) {
                uint32_t addr = bSt + (wn * 64 + np * 16 + laneB_r) * (GPH * 2)
                                    + (laneB_g + 2 * j) * 16;
                LDSM4(bF[np][0], bF[np][1], bF[np][2], bF[np][3], addr);
            }
#pragma unroll
            for (int mt = 0; mt < 4; mt++) {
#pragma unroll
                for (int nt = 0; nt < 8; nt++) {
                    MMA_BF16(acc[mt][nt], aF[mt],
                             bF[nt >> 1][(nt & 1) * 2], bF[nt >> 1][(nt & 1) * 2 + 1]);
                }
            }
        }
    }

    const int rb = lane >> 2;
    const int cb = (lane & 3) * 2;
#pragma unroll
    for (int mt = 0; mt < 4; mt++) {
#pragma unroll
        for (int nt = 0; nt < 8; nt++) {
            int nl = nloc0 + wn * 64 + nt * 8 + cb;
            float2 bv = *(const float2*)(bias + nl);
            int row0 = m0 + wm * 64 + mt * 16 + rb;
            int row1 = row0 + 8;
            float v00 = acc[mt][nt][0] + bv.x;
            float v01 = acc[mt][nt][1] + bv.y;
            float v10 = acc[mt][nt][2] + bv.x;
            float v11 = acc[mt][nt][3] + bv.y;
            if (MODE == 0) {
                *(__nv_bfloat162*)(Cb + (size_t)row0 * D_MODEL + nl) = __floats2bfloat162_rn(v00, v01);
                *(__nv_bfloat162*)(Cb + (size_t)row1 * D_MODEL + nl) = __floats2bfloat162_rn(v10, v11);
            } else {
                float2 r0 = *(const float2*)(resid + (size_t)row0 * D_MODEL + nl);
                float2 r1 = *(const float2*)(resid + (size_t)row1 * D_MODEL + nl);
                *(float2*)(Cf + (size_t)row0 * D_MODEL + nl) = make_float2(v00 + r0.x, v01 + r0.y);
                *(float2*)(Cf + (size_t)row1 * D_MODEL + nl) = make_float2(v10 + r1.x, v11 + r1.y);
            }
        }
    }
}

// ---------------------------------------------------------------------------
// bf16 tensor-core flash attention (fp32 accum + softmax), exp2 domain.
// grid = (SEQ/128, NHEAD, BATCH); 256 threads = 8 warps.
// Softmax runs in log2 space: scores pre-scaled by 0.125*log2(e); exp = ex2.
// Exp of rows 2j,2j+1 is interleaved with PV k16-step j so MUFU drain
// overlaps tensor work. Row sums computed after PV from live s[].
// ---------------------------------------------------------------------------
#define APH    72
#define APB    (APH * 2)            // 144 bytes row pitch
#define KSTG   (64 * APB)           // 9216 per stage
#define AOFF_K  0
#define AOFF_V  (3 * KSTG)           // 27648
#define AOFF_Q  (6 * KSTG)           // 55296
#define ASM_TOTAL (AOFF_Q + 128 * APB) // 73728

#define SCALE_LOG2 0.1803368801111244f   // 0.125 * log2(e)

__global__ __launch_bounds__(256, 2)
void attn_bf16(const __nv_bfloat16* __restrict__ Q,
               const __nv_bfloat16* __restrict__ Kg,
               const __nv_bfloat16* __restrict__ Vg,
               __nv_bfloat16* __restrict__ Og)
{
    extern __shared__ __align__(16) char asmem[];
    const uint32_t sb = s2u(asmem);
    const uint32_t sK = sb + AOFF_K;
    const uint32_t sV = sb + AOFF_V;
    const uint32_t sQ = sb + AOFF_Q;
    __nv_bfloat16* smQ = (__nv_bfloat16*)(asmem + AOFF_Q);

    const int qt   = blockIdx.x;
    const int h    = blockIdx.y;
    const int b    = blockIdx.z;
    const int tid  = threadIdx.x;
    const int warp = tid >> 5;
    const int lane = tid & 31;

    const size_t base = ((size_t)b * SEQ) * D_MODEL + (size_t)h * DHEAD;
    const int NT = SEQ / 64;  // 32

    auto issue_kv = [&](int kt) {
        if (kt < NT) {
            int st = kt - (kt / 3) * 3;
            uint32_t kd = sK + st * KSTG;
            uint32_t vd = sV + st * KSTG;
            const __nv_bfloat16* kp = Kg + base + (size_t)(kt * 64) * D_MODEL;
            const __nv_bfloat16* vp = Vg + base + (size_t)(kt * 64) * D_MODEL;
#pragma unroll
            for (int q = 0; q < 2; q++) {
                int id = tid + q * 256;
                int r = id >> 3, g = id & 7;
                CP16(kd + r * APB + g * 16, kp + (size_t)r * D_MODEL + g * 8);
                CP16(vd + r * APB + g * 16, vp + (size_t)r * D_MODEL + g * 8);
            }
        }
        asm volatile("cp.async.commit_group;" ::: "memory");
    };

    issue_kv(0);
    issue_kv(1);

    // Load Q tile (128 x 64 halves) into smem, then hoist fragments.
    for (int i = tid; i < 1024; i += 256) {
        int r = i >> 3;
        int g = i & 7;
        uint4 f = *(const uint4*)(Q + base + (size_t)(qt * 128 + r) * D_MODEL + g * 8);
        *(uint4*)(smQ + r * APH + g * 8) = f;
    }
    __syncthreads();

    const int laneA_r = ((lane >> 3) & 1) * 8 + (lane & 7);
    const int laneA_g = lane >> 4;
    const int laneB_r = (lane >> 4) * 8 + (lane & 7);
    const int laneB_g = (lane >> 3) & 1;
    const int laneV_key  = ((lane >> 3) & 1) * 8 + (lane & 7);
    const int laneV_doff = (lane >> 4) * 8;

    uint32_t qF[4][4];
#pragma unroll
    for (int j = 0; j < 4; j++) {
        LDSM4(qF[j][0], qF[j][1], qF[j][2], qF[j][3],
              sQ + (warp * 16 + laneA_r) * APB + (laneA_g + 2 * j) * 16);
    }

    // m, l in log2-scaled domain
    float m0 = -1e30f, m1 = -1e30f, l0 = 0.0f, l1 = 0.0f;
    float o[8][4];
#pragma unroll
    for (int nt = 0; nt < 8; nt++)
#pragma unroll
        for (int i = 0; i < 4; i++) o[nt][i] = 0.0f;

    for (int kt = 0; kt < NT; kt++) {
        asm volatile("cp.async.wait_group 1;" ::: "memory");
        __syncthreads();
        issue_kv(kt + 2);

        int st = kt - (kt / 3) * 3;
        uint32_t kSt = sK + st * KSTG;
        uint32_t vSt = sV + st * KSTG;

        // S = Q @ K^T
        float s[8][4];
#pragma unroll
        for (int nt = 0; nt < 8; nt++)
#pragma unroll
            for (int i = 0; i < 4; i++) s[nt][i] = 0.0f;

#pragma unroll
        for (int j = 0; j < 4; j++) {
            uint32_t bF[4][4];
#pragma unroll
            for (int np = 0; np < 4; np++) {
                LDSM4(bF[np][0], bF[np][1], bF[np][2], bF[np][3],
                      kSt + (np * 16 + laneB_r) * APB + (laneB_g + 2 * j) * 16);
            }
#pragma unroll
            for (int nt = 0; nt < 8; nt++)
                MMA_BF16(s[nt], qF[j], bF[nt >> 1][(nt & 1) * 2], bF[nt >> 1][(nt & 1) * 2 + 1]);
        }

        // scale into log2 domain + row max
        float mx0 = -1e30f, mx1 = -1e30f;
#pragma unroll
        for (int nt = 0; nt < 8; nt++) {
            s[nt][0] *= SCALE_LOG2; s[nt][1] *= SCALE_LOG2;
            s[nt][2] *= SCALE_LOG2; s[nt][3] *= SCALE_LOG2;
            mx0 = fmaxf(mx0, fmaxf(s[nt][0], s[nt][1]));
            mx1 = fmaxf(mx1, fmaxf(s[nt][2], s[nt][3]));
        }
        mx0 = fmaxf(mx0, __shfl_xor_sync(0xffffffffu, mx0, 1));
        mx0 = fmaxf(mx0, __shfl_xor_sync(0xffffffffu, mx0, 2));
        mx1 = fmaxf(mx1, __shfl_xor_sync(0xffffffffu, mx1, 1));
        mx1 = fmaxf(mx1, __shfl_xor_sync(0xffffffffu, mx1, 2));
        float nm0 = fmaxf(m0, mx0), nm1 = fmaxf(m1, mx1);
        float a0 = ex2(m0 - nm0), a1 = ex2(m1 - nm1);
        m0 = nm0; m1 = nm1;

        // rescale O before accumulating this tile's PV
#pragma unroll
        for (int nt = 0; nt < 8; nt++) {
            o[nt][0] *= a0; o[nt][1] *= a0;
            o[nt][2] *= a1; o[nt][3] *= a1;
        }
        l0 *= a0;
        l1 *= a1;

        // PV interleaved with exp: step j needs only rows 2j, 2j+1 of P.
#pragma unroll
        for (int j = 0; j < 4; j++) {
#pragma unroll
            for (int u = 0; u < 2; u++) {
                int nt = 2 * j + u;
                s[nt][0] = ex2(s[nt][0] - nm0);
                s[nt][1] = ex2(s[nt][1] - nm0);
                s[nt][2] = ex2(s[nt][2] - nm1);
                s[nt][3] = ex2(s[nt][3] - nm1);
            }
            uint32_t pAj[4];
            pAj[0] = packbf(s[2*j][0],   s[2*j][1]);
            pAj[1] = packbf(s[2*j][2],   s[2*j][3]);
            pAj[2] = packbf(s[2*j+1][0], s[2*j+1][1]);
            pAj[3] = packbf(s[2*j+1][2], s[2*j+1][3]);

            uint32_t tF[4][4];
#pragma unroll
            for (int pr = 0; pr < 4; pr++) {
                uint32_t addr = vSt + (j * 16 + laneV_key) * APB
                                    + (pr * 16 + laneV_doff) * 2;
                LDSM4T(tF[pr][0], tF[pr][1], tF[pr][2], tF[pr][3], addr);
            }
#pragma unroll
            for (int nt = 0; nt < 8; nt++)
                MMA_BF16(o[nt], pAj, tF[nt >> 1][(nt & 1) * 2], tF[nt >> 1][(nt & 1) * 2 + 1]);
        }

        // row sums from live exp'ed s[]
        float sum0 = 0.0f, sum1 = 0.0f;
#pragma unroll
        for (int nt = 0; nt < 8; nt++) {
            sum0 += s[nt][0] + s[nt][1];
            sum1 += s[nt][2] + s[nt][3];
        }
        sum0 += __shfl_xor_sync(0xffffffffu, sum0, 1);
        sum0 += __shfl_xor_sync(0xffffffffu, sum0, 2);
        sum1 += __shfl_xor_sync(0xffffffffu, sum1, 1);
        sum1 += __shfl_xor_sync(0xffffffffu, sum1, 2);
        l0 += sum0;
        l1 += sum1;
        // no trailing barrier: 3-stage ring; refill fenced by top-of-loop sync.
    }

    // Epilogue: normalize, convert bf16
    float inv0 = 1.0f / l0, inv1 = 1.0f / l1;
    int r0 = qt * 128 + warp * 16 + (lane >> 2);
    int c0 = (lane & 3) * 2;
#pragma unroll
    for (int nt = 0; nt < 8; nt++) {
        size_t p0 = base + (size_t)r0 * D_MODEL + nt * 8 + c0;
        size_t p1 = base + (size_t)(r0 + 8) * D_MODEL + nt * 8 + c0;
        *(__nv_bfloat162*)(Og + p0) = __floats2bfloat162_rn(o[nt][0] * inv0, o[nt][1] * inv0);
        *(__nv_bfloat162*)(Og + p1) = __floats2bfloat162_rn(o[nt][2] * inv1, o[nt][3] * inv1);
    }
}

// ---------------------------------------------------------------------------
// LayerNorm
// ---------------------------------------------------------------------------
__global__ __launch_bounds__(256)
void ln_kernel(const float* __restrict__ X,
               const float* __restrict__ gamma,
               const float* __restrict__ beta,
               float* __restrict__ out)
{
    const int row = blockIdx.x;
    const int tid = threadIdx.x;
    const float* x = X + (size_t)row * D_MODEL;

    float4 f = *(const float4*)(x + tid * 4);
    float s  = f.x + f.y + f.z + f.w;
    float ss = f.x * f.x + f.y * f.y + f.z * f.z + f.w * f.w;

#pragma unroll
    for (int o = 16; o > 0; o >>= 1) {
        s  += __shfl_xor_sync(0xffffffffu, s,  o);
        ss += __shfl_xor_sync(0xffffffffu, ss, o);
    }

    __shared__ float sh[16];
    const int warp = tid >> 5, lane = tid & 31;
    if (lane == 0) { sh[warp] = s; sh[warp + 8] = ss; }
    __syncthreads();
    if (tid == 0) {
        float S = 0.0f, SS = 0.0f;
#pragma unroll
        for (int w = 0; w < 8; w++) { S += sh[w]; SS += sh[w + 8]; }
        float mu  = S * (1.0f / D_MODEL);
        float var = SS * (1.0f / D_MODEL) - mu * mu;
        sh[0] = mu;
        sh[1] = rsqrtf(var + LN_EPS);
    }
    __syncthreads();
    float mu = sh[0], rstd = sh[1];

    float4 gm = *(const float4*)(gamma + tid * 4);
    float4 bt = *(const float4*)(beta  + tid * 4);
    float4 o4;
    o4.x = (f.x - mu) * rstd * gm.x + bt.x;
    o4.y = (f.y - mu) * rstd * gm.y + bt.y;
    o4.z = (f.z - mu) * rstd * gm.z + bt.z;
    o4.w = (f.w - mu) * rstd * gm.w + bt.w;
    *(float4*)(out + (size_t)row * D_MODEL + tid * 4) = o4;
}

// ---------------------------------------------------------------------------
// Launch
// ---------------------------------------------------------------------------
extern "C" void kernel_launch(void* const* d_in, const int* in_sizes, int n_in,
                              void* d_out, int out_size)
{
    const float* batch = (const float*)d_in[0];
    const float* wq    = (const float*)d_in[1];
    const float* bq    = (const float*)d_in[2];
    const float* wk    = (const float*)d_in[3];
    const float* bk    = (const float*)d_in[4];
    const float* wv    = (const float*)d_in[5];
    const float* bv    = (const float*)d_in[6];
    const float* wo    = (const float*)d_in[7];
    const float* bo    = (const float*)d_in[8];
    const float* ln_g  = (const float*)d_in[9];
    const float* ln_b  = (const float*)d_in[10];

    __nv_bfloat16 *qh, *kh, *vh, *ah, *bxh, *wqkvh, *woh;
    float *x;
    cudaGetSymbolAddress((void**)&qh,    g_qh);
    cudaGetSymbolAddress((void**)&kh,    g_kh);
    cudaGetSymbolAddress((void**)&vh,    g_vh);
    cudaGetSymbolAddress((void**)&ah,    g_ah);
    cudaGetSymbolAddress((void**)&bxh,   g_bxh);
    cudaGetSymbolAddress((void**)&wqkvh, g_wqkv);
    cudaGetSymbolAddress((void**)&woh,   g_woh);
    cudaGetSymbolAddress((void**)&x,     g_x);

    static bool attr_done = false;
    if (!attr_done) {
        cudaFuncSetAttribute(gemm_bf16<0>, cudaFuncAttributeMaxDynamicSharedMemorySize, GSM);
        cudaFuncSetAttribute(gemm_bf16<1>, cudaFuncAttributeMaxDynamicSharedMemorySize, GSM);
        cudaFuncSetAttribute(attn_bf16, cudaFuncAttributeMaxDynamicSharedMemorySize, ASM_TOTAL);
        attr_done = true;
    }

    // fp32 -> bf16 conversions (3 launches)
    const int nb4 = MTOT * D_MODEL / 4;
    const int nw4 = D_MODEL * D_MODEL / 4;
    conv_bf16_kernel<<<(nb4 + 255) / 256, 256>>>(batch, bxh, nb4);
    conv_wqkv_kernel<<<(3 * nw4 + 255) / 256, 256>>>(wq, wk, wv, wqkvh);
    conv_bf16_kernel<<<(nw4 + 255) / 256, 256>>>(wo, woh, nw4);

    // Fused QKV projection: [8192,1024] @ [3072,1024]^T
    dim3 gq(3 * D_MODEL / 128, MTOT / 128);  // (24, 64)
    gemm_bf16<0><<<gq, 128, GSM>>>(bxh, wqkvh, bq, bk, bv, qh, kh, vh,
                                   nullptr, nullptr, MTOT, D_MODEL);

    dim3 ga(SEQ / 128, NHEAD, BATCH);        // (16, 16, 4)
    attn_bf16<<<ga, 256, ASM_TOTAL>>>(qh, kh, vh, ah);

    // Out-projection + residual (fp32 out)
    dim3 gg(D_MODEL / 128, MTOT / 128);      // (8, 64)
    gemm_bf16<1><<<gg, 128, GSM>>>(ah, woh, bo, nullptr, nullptr,
                                   nullptr, nullptr, nullptr, batch, x,
                                   MTOT, D_MODEL);

    ln_kernel<<<MTOT, 256>>>(x, ln_g, ln_b, (float*)d_out);
}

// round 11
// speedup vs baseline: 11.0488x; 1.0070x over previous
#include <cuda_runtime.h>
#include <cuda_bf16.h>
#include <cstdint>

#define D_MODEL 1024
#define SEQ     2048
#define BATCH   4
#define NHEAD   16
#define DHEAD   64
#define MTOT    (BATCH*SEQ)   // 8192
#define LN_EPS  1e-5f

// ---------------------------------------------------------------------------
// Scratch (no cudaMalloc allowed). bf16 operands, fp32 where accuracy matters.
// ---------------------------------------------------------------------------
__device__ __nv_bfloat16 g_qh[(size_t)MTOT * D_MODEL];
__device__ __nv_bfloat16 g_kh[(size_t)MTOT * D_MODEL];
__device__ __nv_bfloat16 g_vh[(size_t)MTOT * D_MODEL];
__device__ __nv_bfloat16 g_ah[(size_t)MTOT * D_MODEL];   // attention output
__device__ __nv_bfloat16 g_bxh[(size_t)MTOT * D_MODEL];  // bf16 batch
__device__ __nv_bfloat16 g_wqkv[(size_t)3 * D_MODEL * D_MODEL]; // packed q,k,v
__device__ __nv_bfloat16 g_woh[(size_t)D_MODEL * D_MODEL];
__device__ float g_x[(size_t)MTOT * D_MODEL];            // residual sum (fp32)

// ---------------------------------------------------------------------------
// Helpers
// ---------------------------------------------------------------------------
__device__ __forceinline__ uint32_t s2u(const void* p) {
    uint32_t a;
    asm("{ .reg .u64 t; cvta.to.shared.u64 t, %1; cvt.u32.u64 %0, t; }"
        : "=r"(a) : "l"(p));
    return a;
}

#define LDSM4(f0,f1,f2,f3,addr) \
    asm volatile("ldmatrix.sync.aligned.m8n8.x4.shared.b16 {%0,%1,%2,%3}, [%4];" \
                 : "=r"(f0), "=r"(f1), "=r"(f2), "=r"(f3) : "r"(addr))

#define LDSM4T(f0,f1,f2,f3,addr) \
    asm volatile("ldmatrix.sync.aligned.m8n8.x4.trans.shared.b16 {%0,%1,%2,%3}, [%4];" \
                 : "=r"(f0), "=r"(f1), "=r"(f2), "=r"(f3) : "r"(addr))

#define MMA_BF16(d, a, b0, b1) \
    asm volatile("mma.sync.aligned.m16n8k16.row.col.f32.bf16.bf16.f32 " \
                 "{%0,%1,%2,%3}, {%4,%5,%6,%7}, {%8,%9}, {%0,%1,%2,%3};" \
                 : "+f"((d)[0]), "+f"((d)[1]), "+f"((d)[2]), "+f"((d)[3]) \
                 : "r"((a)[0]), "r"((a)[1]), "r"((a)[2]), "r"((a)[3]), \
                   "r"(b0), "r"(b1))

#define CP16(dst, src) \
    asm volatile("cp.async.cg.shared.global [%0], [%1], 16;" \
                 :: "r"(dst), "l"(src) : "memory")

__device__ __forceinline__ uint32_t packbf(float a, float b) {
    __nv_bfloat162 h = __floats2bfloat162_rn(a, b);
    return *(uint32_t*)&h;
}

// Raw MUFU exp2 (single EX2, no pre-multiply)
__device__ __forceinline__ float ex2(float x) {
    float r;
    asm("ex2.approx.f32 %0, %1;" : "=f"(r) : "f"(x));
    return r;
}

// ---------------------------------------------------------------------------
// Single fused fp32 -> bf16 conversion kernel:
//   segment 0: batch  -> g_bxh            (nb4 float4s)
//   segment 1: wq/wk/wv -> g_wqkv packed  (3*nw4 float4s)
//   segment 2: wo     -> g_woh            (nw4 float4s)
// ---------------------------------------------------------------------------
__global__ __launch_bounds__(256)
void conv_all_kernel(const float* __restrict__ batch,
                     const float* __restrict__ wq, const float* __restrict__ wk,
                     const float* __restrict__ wv, const float* __restrict__ wo,
                     __nv_bfloat16* __restrict__ bxh,
                     __nv_bfloat16* __restrict__ wqkv,
                     __nv_bfloat16* __restrict__ woh)
{
    const int nb4 = MTOT * D_MODEL / 4;
    const int nw4 = D_MODEL * D_MODEL / 4;
    int i = blockIdx.x * blockDim.x + threadIdx.x;

    const float* src;
    __nv_bfloat16* dst;
    int j;
    if (i < nb4) {
        src = batch; dst = bxh; j = i;
    } else {
        int k = i - nb4;
        if (k < 3 * nw4) {
            int w = k / nw4;
            j = k - w * nw4;
            src = (w == 0) ? wq : (w == 1) ? wk : wv;
            dst = wqkv + (size_t)w * D_MODEL * D_MODEL;
        } else {
            j = k - 3 * nw4;
            if (j >= nw4) return;
            src = wo; dst = woh;
        }
    }
    float4 f = ((const float4*)src)[j];
    ((__nv_bfloat162*)dst)[j * 2]     = __floats2bfloat162_rn(f.x, f.y);
    ((__nv_bfloat162*)dst)[j * 2 + 1] = __floats2bfloat162_rn(f.z, f.w);
}

// ---------------------------------------------------------------------------
// bf16 mma GEMM. MODE 0: fused QKV. MODE 1: out-proj (fp32 out + residual).
// CTA tile 128x128, 128 threads = 4 warps, warp tile 64x64 (2x2 warp grid).
// BK=64 halves, NS=3 cp.async stages, one __syncthreads per chunk.
// UNCHANGED from Round 9/10 — empirically at the sm_103 mma.sync ceiling.
// ---------------------------------------------------------------------------
#define GPH   72                    // halves per smem row (64 data + 8 pad)
#define GSTGB (128 * GPH * 2)       // 18432 bytes per operand per stage
#define GSM   (3 * 2 * GSTGB)       // 110592 bytes dynamic smem

template<int MODE>
__global__ __launch_bounds__(128, 2)
void gemm_bf16(const __nv_bfloat16* __restrict__ A, const __nv_bfloat16* __restrict__ W,
               const float* __restrict__ b0p, const float* __restrict__ b1p,
               const float* __restrict__ b2p,
               __nv_bfloat16* __restrict__ o0p, __nv_bfloat16* __restrict__ o1p,
               __nv_bfloat16* __restrict__ o2p,
               const float* __restrict__ resid, float* __restrict__ Cf,
               int M, int K)
{
    extern __shared__ __align__(16) char gsm[];
    const uint32_t sA = s2u(gsm);
    const uint32_t sB = sA + 3 * GSTGB;

    const int tid  = threadIdx.x;
    const int wid  = tid >> 5;
    const int lane = tid & 31;
    const int wm   = wid & 1;
    const int wn   = wid >> 1;
    const int m0   = blockIdx.y * 128;
    const int n0   = blockIdx.x * 128;
    const int NCH  = K / 64;               // 16

    const float* bias;
    __nv_bfloat16* Cb = nullptr;
    int nloc0;
    if (MODE == 0) {
        int seg = n0 >> 10;
        bias  = (seg == 0) ? b0p : (seg == 1) ? b1p : b2p;
        Cb    = (seg == 0) ? o0p : (seg == 1) ? o1p : o2p;
        nloc0 = n0 & 1023;
    } else {
        bias  = b0p;
        nloc0 = n0;
    }

    const int r_ld = tid >> 3;
    const int g_ld = tid & 7;
    const __nv_bfloat16* Abase = A + (size_t)m0 * K + g_ld * 8;
    const __nv_bfloat16* Wbase = W + (size_t)n0 * K + g_ld * 8;

    auto issue = [&](int c) {
        if (c < NCH) {
            int st = c - (c / 3) * 3;
            uint32_t da = sA + st * GSTGB;
            uint32_t db = sB + st * GSTGB;
            long ko = (long)c * 64;
#pragma unroll
            for (int q = 0; q < 8; q++) {
                int row = r_ld + q * 16;
                CP16(da + row * (GPH * 2) + g_ld * 16, Abase + (size_t)row * K + ko);
                CP16(db + row * (GPH * 2) + g_ld * 16, Wbase + (size_t)row * K + ko);
            }
        }
        asm volatile("cp.async.commit_group;" ::: "memory");
    };

    float acc[4][8][4];
#pragma unroll
    for (int i = 0; i < 4; i++)
#pragma unroll
        for (int j = 0; j < 8; j++)
#pragma unroll
            for (int k = 0; k < 4; k++) acc[i][j][k] = 0.0f;

    const int laneA_r = ((lane >> 3) & 1) * 8 + (lane & 7);
    const int laneA_g = lane >> 4;
    const int laneB_r = (lane >> 4) * 8 + (lane & 7);
    const int laneB_g = (lane >> 3) & 1;

    issue(0); issue(1);

    for (int c = 0; c < NCH; c++) {
        asm volatile("cp.async.wait_group 1;" ::: "memory");
        __syncthreads();
        issue(c + 2);

        int st = c - (c / 3) * 3;
        uint32_t aSt = sA + st * GSTGB;
        uint32_t bSt = sB + st * GSTGB;

#pragma unroll
        for (int j = 0; j < 4; j++) {
            uint32_t aF[4][4], bF[4][4];
#pragma unroll
            for (int mt = 0; mt < 4; mt++) {
                uint32_t addr = aSt + (wm * 64 + mt * 16 + laneA_r) * (GPH * 2)
                                    + (laneA_g + 2 * j) * 16;
                LDSM4(aF[mt][0], aF[mt][1], aF[mt][2], aF[mt][3], addr);
            }
#pragma unroll
            for (int np = 0; np < 4; np++) {
                uint32_t addr = bSt + (wn * 64 + np * 16 + laneB_r) * (GPH * 2)
                                    + (laneB_g + 2 * j) * 16;
                LDSM4(bF[np][0], bF[np][1], bF[np][2], bF[np][3], addr);
            }
#pragma unroll
            for (int mt = 0; mt < 4; mt++) {
#pragma unroll
                for (int nt = 0; nt < 8; nt++) {
                    MMA_BF16(acc[mt][nt], aF[mt],
                             bF[nt >> 1][(nt & 1) * 2], bF[nt >> 1][(nt & 1) * 2 + 1]);
                }
            }
        }
    }

    const int rb = lane >> 2;
    const int cb = (lane & 3) * 2;
#pragma unroll
    for (int mt = 0; mt < 4; mt++) {
#pragma unroll
        for (int nt = 0; nt < 8; nt++) {
            int nl = nloc0 + wn * 64 + nt * 8 + cb;
            float2 bv = *(const float2*)(bias + nl);
            int row0 = m0 + wm * 64 + mt * 16 + rb;
            int row1 = row0 + 8;
            float v00 = acc[mt][nt][0] + bv.x;
            float v01 = acc[mt][nt][1] + bv.y;
            float v10 = acc[mt][nt][2] + bv.x;
            float v11 = acc[mt][nt][3] + bv.y;
            if (MODE == 0) {
                *(__nv_bfloat162*)(Cb + (size_t)row0 * D_MODEL + nl) = __floats2bfloat162_rn(v00, v01);
                *(__nv_bfloat162*)(Cb + (size_t)row1 * D_MODEL + nl) = __floats2bfloat162_rn(v10, v11);
            } else {
                float2 r0 = *(const float2*)(resid + (size_t)row0 * D_MODEL + nl);
                float2 r1 = *(const float2*)(resid + (size_t)row1 * D_MODEL + nl);
                *(float2*)(Cf + (size_t)row0 * D_MODEL + nl) = make_float2(v00 + r0.x, v01 + r0.y);
                *(float2*)(Cf + (size_t)row1 * D_MODEL + nl) = make_float2(v10 + r1.x, v11 + r1.y);
            }
        }
    }
}

// ---------------------------------------------------------------------------
// bf16 tensor-core flash attention (fp32 accum + softmax), exp2 domain.
// UNCHANGED from Round 10 (at the same mma.sync plateau).
// ---------------------------------------------------------------------------
#define APH    72
#define APB    (APH * 2)            // 144 bytes row pitch
#define KSTG   (64 * APB)           // 9216 per stage
#define AOFF_K  0
#define AOFF_V  (3 * KSTG)           // 27648
#define AOFF_Q  (6 * KSTG)           // 55296
#define ASM_TOTAL (AOFF_Q + 128 * APB) // 73728

#define SCALE_LOG2 0.1803368801111244f   // 0.125 * log2(e)

__global__ __launch_bounds__(256, 2)
void attn_bf16(const __nv_bfloat16* __restrict__ Q,
               const __nv_bfloat16* __restrict__ Kg,
               const __nv_bfloat16* __restrict__ Vg,
               __nv_bfloat16* __restrict__ Og)
{
    extern __shared__ __align__(16) char asmem[];
    const uint32_t sb = s2u(asmem);
    const uint32_t sK = sb + AOFF_K;
    const uint32_t sV = sb + AOFF_V;
    const uint32_t sQ = sb + AOFF_Q;
    __nv_bfloat16* smQ = (__nv_bfloat16*)(asmem + AOFF_Q);

    const int qt   = blockIdx.x;
    const int h    = blockIdx.y;
    const int b    = blockIdx.z;
    const int tid  = threadIdx.x;
    const int warp = tid >> 5;
    const int lane = tid & 31;

    const size_t base = ((size_t)b * SEQ) * D_MODEL + (size_t)h * DHEAD;
    const int NT = SEQ / 64;  // 32

    auto issue_kv = [&](int kt) {
        if (kt < NT) {
            int st = kt - (kt / 3) * 3;
            uint32_t kd = sK + st * KSTG;
            uint32_t vd = sV + st * KSTG;
            const __nv_bfloat16* kp = Kg + base + (size_t)(kt * 64) * D_MODEL;
            const __nv_bfloat16* vp = Vg + base + (size_t)(kt * 64) * D_MODEL;
#pragma unroll
            for (int q = 0; q < 2; q++) {
                int id = tid + q * 256;
                int r = id >> 3, g = id & 7;
                CP16(kd + r * APB + g * 16, kp + (size_t)r * D_MODEL + g * 8);
                CP16(vd + r * APB + g * 16, vp + (size_t)r * D_MODEL + g * 8);
            }
        }
        asm volatile("cp.async.commit_group;" ::: "memory");
    };

    issue_kv(0);
    issue_kv(1);

    for (int i = tid; i < 1024; i += 256) {
        int r = i >> 3;
        int g = i & 7;
        uint4 f = *(const uint4*)(Q + base + (size_t)(qt * 128 + r) * D_MODEL + g * 8);
        *(uint4*)(smQ + r * APH + g * 8) = f;
    }
    __syncthreads();

    const int laneA_r = ((lane >> 3) & 1) * 8 + (lane & 7);
    const int laneA_g = lane >> 4;
    const int laneB_r = (lane >> 4) * 8 + (lane & 7);
    const int laneB_g = (lane >> 3) & 1;
    const int laneV_key  = ((lane >> 3) & 1) * 8 + (lane & 7);
    const int laneV_doff = (lane >> 4) * 8;

    uint32_t qF[4][4];
#pragma unroll
    for (int j = 0; j < 4; j++) {
        LDSM4(qF[j][0], qF[j][1], qF[j][2], qF[j][3],
              sQ + (warp * 16 + laneA_r) * APB + (laneA_g + 2 * j) * 16);
    }

    float m0 = -1e30f, m1 = -1e30f, l0 = 0.0f, l1 = 0.0f;
    float o[8][4];
#pragma unroll
    for (int nt = 0; nt < 8; nt++)
#pragma unroll
        for (int i = 0; i < 4; i++) o[nt][i] = 0.0f;

    for (int kt = 0; kt < NT; kt++) {
        asm volatile("cp.async.wait_group 1;" ::: "memory");
        __syncthreads();
        issue_kv(kt + 2);

        int st = kt - (kt / 3) * 3;
        uint32_t kSt = sK + st * KSTG;
        uint32_t vSt = sV + st * KSTG;

        float s[8][4];
#pragma unroll
        for (int nt = 0; nt < 8; nt++)
#pragma unroll
            for (int i = 0; i < 4; i++) s[nt][i] = 0.0f;

#pragma unroll
        for (int j = 0; j < 4; j++) {
            uint32_t bF[4][4];
#pragma unroll
            for (int np = 0; np < 4; np++) {
                LDSM4(bF[np][0], bF[np][1], bF[np][2], bF[np][3],
                      kSt + (np * 16 + laneB_r) * APB + (laneB_g + 2 * j) * 16);
            }
#pragma unroll
            for (int nt = 0; nt < 8; nt++)
                MMA_BF16(s[nt], qF[j], bF[nt >> 1][(nt & 1) * 2], bF[nt >> 1][(nt & 1) * 2 + 1]);
        }

        float mx0 = -1e30f, mx1 = -1e30f;
#pragma unroll
        for (int nt = 0; nt < 8; nt++) {
            s[nt][0] *= SCALE_LOG2; s[nt][1] *= SCALE_LOG2;
            s[nt][2] *= SCALE_LOG2; s[nt][3] *= SCALE_LOG2;
            mx0 = fmaxf(mx0, fmaxf(s[nt][0], s[nt][1]));
            mx1 = fmaxf(mx1, fmaxf(s[nt][2], s[nt][3]));
        }
        mx0 = fmaxf(mx0, __shfl_xor_sync(0xffffffffu, mx0, 1));
        mx0 = fmaxf(mx0, __shfl_xor_sync(0xffffffffu, mx0, 2));
        mx1 = fmaxf(mx1, __shfl_xor_sync(0xffffffffu, mx1, 1));
        mx1 = fmaxf(mx1, __shfl_xor_sync(0xffffffffu, mx1, 2));
        float nm0 = fmaxf(m0, mx0), nm1 = fmaxf(m1, mx1);
        float a0 = ex2(m0 - nm0), a1 = ex2(m1 - nm1);
        m0 = nm0; m1 = nm1;

#pragma unroll
        for (int nt = 0; nt < 8; nt++) {
            o[nt][0] *= a0; o[nt][1] *= a0;
            o[nt][2] *= a1; o[nt][3] *= a1;
        }
        l0 *= a0;
        l1 *= a1;

#pragma unroll
        for (int j = 0; j < 4; j++) {
#pragma unroll
            for (int u = 0; u < 2; u++) {
                int nt = 2 * j + u;
                s[nt][0] = ex2(s[nt][0] - nm0);
                s[nt][1] = ex2(s[nt][1] - nm0);
                s[nt][2] = ex2(s[nt][2] - nm1);
                s[nt][3] = ex2(s[nt][3] - nm1);
            }
            uint32_t pAj[4];
            pAj[0] = packbf(s[2*j][0],   s[2*j][1]);
            pAj[1] = packbf(s[2*j][2],   s[2*j][3]);
            pAj[2] = packbf(s[2*j+1][0], s[2*j+1][1]);
            pAj[3] = packbf(s[2*j+1][2], s[2*j+1][3]);

            uint32_t tF[4][4];
#pragma unroll
            for (int pr = 0; pr < 4; pr++) {
                uint32_t addr = vSt + (j * 16 + laneV_key) * APB
                                    + (pr * 16 + laneV_doff) * 2;
                LDSM4T(tF[pr][0], tF[pr][1], tF[pr][2], tF[pr][3], addr);
            }
#pragma unroll
            for (int nt = 0; nt < 8; nt++)
                MMA_BF16(o[nt], pAj, tF[nt >> 1][(nt & 1) * 2], tF[nt >> 1][(nt & 1) * 2 + 1]);
        }

        float sum0 = 0.0f, sum1 = 0.0f;
#pragma unroll
        for (int nt = 0; nt < 8; nt++) {
            sum0 += s[nt][0] + s[nt][1];
            sum1 += s[nt][2] + s[nt][3];
        }
        sum0 += __shfl_xor_sync(0xffffffffu, sum0, 1);
        sum0 += __shfl_xor_sync(0xffffffffu, sum0, 2);
        sum1 += __shfl_xor_sync(0xffffffffu, sum1, 1);
        sum1 += __shfl_xor_sync(0xffffffffu, sum1, 2);
        l0 += sum0;
        l1 += sum1;
    }

    float inv0 = 1.0f / l0, inv1 = 1.0f / l1;
    int r0 = qt * 128 + warp * 16 + (lane >> 2);
    int c0 = (lane & 3) * 2;
#pragma unroll
    for (int nt = 0; nt < 8; nt++) {
        size_t p0 = base + (size_t)r0 * D_MODEL + nt * 8 + c0;
        size_t p1 = base + (size_t)(r0 + 8) * D_MODEL + nt * 8 + c0;
        *(__nv_bfloat162*)(Og + p0) = __floats2bfloat162_rn(o[nt][0] * inv0, o[nt][1] * inv0);
        *(__nv_bfloat162*)(Og + p1) = __floats2bfloat162_rn(o[nt][2] * inv1, o[nt][3] * inv1);
    }
}

// ---------------------------------------------------------------------------
// LayerNorm: 4 rows per block (2048 blocks x 256 threads).
// gamma/beta loaded once into registers and reused across the 4 rows.
// ---------------------------------------------------------------------------
__global__ __launch_bounds__(256)
void ln_kernel(const float* __restrict__ X,
               const float* __restrict__ gamma,
               const float* __restrict__ beta,
               float* __restrict__ out)
{
    const int tid  = threadIdx.x;
    const int warp = tid >> 5, lane = tid & 31;

    float4 gm = *(const float4*)(gamma + tid * 4);
    float4 bt = *(const float4*)(beta  + tid * 4);

    __shared__ float sh[16];

#pragma unroll
    for (int rr = 0; rr < 4; rr++) {
        const int row = blockIdx.x * 4 + rr;
        const float* x = X + (size_t)row * D_MODEL;

        float4 f = *(const float4*)(x + tid * 4);
        float s  = f.x + f.y + f.z + f.w;
        float ss = f.x * f.x + f.y * f.y + f.z * f.z + f.w * f.w;

#pragma unroll
        for (int o = 16; o > 0; o >>= 1) {
            s  += __shfl_xor_sync(0xffffffffu, s,  o);
            ss += __shfl_xor_sync(0xffffffffu, ss, o);
        }
        if (lane == 0) { sh[warp] = s; sh[warp + 8] = ss; }
        __syncthreads();
        if (tid == 0) {
            float S = 0.0f, SS = 0.0f;
#pragma unroll
            for (int w = 0; w < 8; w++) { S += sh[w]; SS += sh[w + 8]; }
            float mu  = S * (1.0f / D_MODEL);
            float var = SS * (1.0f / D_MODEL) - mu * mu;
            sh[0] = mu;
            sh[1] = rsqrtf(var + LN_EPS);
        }
        __syncthreads();
        float mu = sh[0], rstd = sh[1];
        __syncthreads();   // sh reusable next row after all threads read

        float4 o4;
        o4.x = (f.x - mu) * rstd * gm.x + bt.x;
        o4.y = (f.y - mu) * rstd * gm.y + bt.y;
        o4.z = (f.z - mu) * rstd * gm.z + bt.z;
        o4.w = (f.w - mu) * rstd * gm.w + bt.w;
        *(float4*)(out + (size_t)row * D_MODEL + tid * 4) = o4;
    }
}

// ---------------------------------------------------------------------------
// Launch
// ---------------------------------------------------------------------------
extern "C" void kernel_launch(void* const* d_in, const int* in_sizes, int n_in,
                              void* d_out, int out_size)
{
    const float* batch = (const float*)d_in[0];
    const float* wq    = (const float*)d_in[1];
    const float* bq    = (const float*)d_in[2];
    const float* wk    = (const float*)d_in[3];
    const float* bk    = (const float*)d_in[4];
    const float* wv    = (const float*)d_in[5];
    const float* bv    = (const float*)d_in[6];
    const float* wo    = (const float*)d_in[7];
    const float* bo    = (const float*)d_in[8];
    const float* ln_g  = (const float*)d_in[9];
    const float* ln_b  = (const float*)d_in[10];

    __nv_bfloat16 *qh, *kh, *vh, *ah, *bxh, *wqkvh, *woh;
    float *x;
    cudaGetSymbolAddress((void**)&qh,    g_qh);
    cudaGetSymbolAddress((void**)&kh,    g_kh);
    cudaGetSymbolAddress((void**)&vh,    g_vh);
    cudaGetSymbolAddress((void**)&ah,    g_ah);
    cudaGetSymbolAddress((void**)&bxh,   g_bxh);
    cudaGetSymbolAddress((void**)&wqkvh, g_wqkv);
    cudaGetSymbolAddress((void**)&woh,   g_woh);
    cudaGetSymbolAddress((void**)&x,     g_x);

    static bool attr_done = false;
    if (!attr_done) {
        cudaFuncSetAttribute(gemm_bf16<0>, cudaFuncAttributeMaxDynamicSharedMemorySize, GSM);
        cudaFuncSetAttribute(gemm_bf16<1>, cudaFuncAttributeMaxDynamicSharedMemorySize, GSM);
        cudaFuncSetAttribute(attn_bf16, cudaFuncAttributeMaxDynamicSharedMemorySize, ASM_TOTAL);
        attr_done = true;
    }

    // Single fused fp32 -> bf16 conversion launch
    const int nb4 = MTOT * D_MODEL / 4;
    const int nw4 = D_MODEL * D_MODEL / 4;
    const int ntot = nb4 + 4 * nw4;
    conv_all_kernel<<<(ntot + 255) / 256, 256>>>(batch, wq, wk, wv, wo,
                                                 bxh, wqkvh, woh);

    // Fused QKV projection: [8192,1024] @ [3072,1024]^T
    dim3 gq(3 * D_MODEL / 128, MTOT / 128);  // (24, 64)
    gemm_bf16<0><<<gq, 128, GSM>>>(bxh, wqkvh, bq, bk, bv, qh, kh, vh,
                                   nullptr, nullptr, MTOT, D_MODEL);

    dim3 ga(SEQ / 128, NHEAD, BATCH);        // (16, 16, 4)
    attn_bf16<<<ga, 256, ASM_TOTAL>>>(qh, kh, vh, ah);

    // Out-projection + residual (fp32 out)
    dim3 gg(D_MODEL / 128, MTOT / 128);      // (8, 64)
    gemm_bf16<1><<<gg, 128, GSM>>>(ah, woh, bo, nullptr, nullptr,
                                   nullptr, nullptr, nullptr, batch, x,
                                   MTOT, D_MODEL);

    ln_kernel<<<MTOT / 4, 256>>>(x, ln_g, ln_b, (float*)d_out);
}